// round 2
// baseline (speedup 1.0000x reference)
#include <cuda_runtime.h>
#include <math.h>

#define B_  4
#define H_  8
#define N_  1024
#define DH_ 128
#define BH_ (B_*H_)

#define BM   128
#define KC   16
#define PADW 132
#define SCALE_Q 0.08838834764831845f  /* 1/sqrt(128) */

__device__ float g_sc[BH_];
__device__ float g_inv[BH_*N_];

__device__ __forceinline__ float softplus_ref(float x){
    return fmaxf(x, 0.0f) + log1pf(__expf(-fabsf(x)));
}

// softplus(-y) = max(-y,0) + log1p(exp(-|y|)), MUFU-free (FMA/ALU only).
__device__ __forceinline__ float softplus_neg_fast(float y){
    float ax = fabsf(y);
    float z  = fmaxf(ax * -1.4426950408889634f, -80.0f);   // z = -|y|*log2(e)
    // split z = r + f, r = round(z), f in [-0.5, 0.5] (magic-number rint)
    float fz = z + 12582912.0f;                             // 1.5 * 2^23
    int   ri = __float_as_int(fz);
    float r  = fz - 12582912.0f;
    float f  = z - r;
    // 2^f, Taylor of exp(f*ln2), deg 6, |err| ~ 1e-7 on [-0.5,0.5]
    float p  = 1.5403530e-4f;
    p = fmaf(p, f, 1.3333558e-3f);
    p = fmaf(p, f, 9.6181291e-3f);
    p = fmaf(p, f, 5.5504109e-2f);
    p = fmaf(p, f, 2.4022651e-1f);
    p = fmaf(p, f, 6.9314718e-1f);
    p = fmaf(p, f, 1.0f);
    int e = (ri & 0x7FFFFF) - 0x400000;                     // = round(z), in [-80,0]
    float t = __int_as_float(__float_as_int(p) + (e << 23)); // t = exp(-|y|) in (0,1]
    // log1p(t) = 2*atanh(s), s = t/(t+2); 1/(t+2) via linear seed + 2 Newton (no MUFU)
    float d  = t + 2.0f;
    float rc = fmaf(-0.16666667f, d, 0.8249f);
    rc = rc * fmaf(-d, rc, 2.0f);
    rc = rc * fmaf(-d, rc, 2.0f);
    float s  = t * rc;
    float s2 = s * s;
    float qq = fmaf(s2, fmaf(s2, fmaf(s2, fmaf(s2, 0.11111111f, 0.14285715f),
                                      0.2f), 0.33333334f), 1.0f);
    float l  = 2.0f * s * qq;
    return fmaxf(-y, 0.0f) + l;
}

// ---- kernel A: g_sc[bh] = sum_n softplus(c[bh][n]) ----
__global__ void k_sc(const float* __restrict__ c){
    const int bh  = blockIdx.x;
    const int tid = threadIdx.x;
    const float* cp = c + (size_t)bh * N_;
    float s = 0.0f;
    for (int i = tid; i < N_; i += 256) s += softplus_ref(cp[i]);
    #pragma unroll
    for (int o = 16; o; o >>= 1) s += __shfl_xor_sync(0xffffffffu, s, o);
    __shared__ float red[8];
    if ((tid & 31) == 0) red[tid >> 5] = s;
    __syncthreads();
    if (tid == 0){
        float t = 0.0f;
        #pragma unroll
        for (int i = 0; i < 8; i++) t += red[i];
        g_sc[bh] = t;
    }
}

// ---- main fused kernel ----
extern __shared__ float smem_f[];

__global__ __launch_bounds__(256, 1)
void k_main(const float* __restrict__ q, const float* __restrict__ k,
            const float* __restrict__ v, const float* __restrict__ d_q,
            const float* __restrict__ d_k,
            const float* __restrict__ w_w, const float* __restrict__ b_w,
            const float* __restrict__ w_b, const float* __restrict__ b_b,
            float* __restrict__ out, float* __restrict__ scores)
{
    const int bh = blockIdx.x >> 3;
    const int rt = blockIdx.x & 7;
    const int b  = bh >> 3;
    const int h  = bh & 7;
    const int n0 = rt * BM;
    const int tid = threadIdx.x;
    const int tx = tid & 15, ty = tid >> 4;

    float* sA   = smem_f;                 // [KC][PADW]  Q chunk (k-major, pre-scaled)
    float* sB   = sA + KC * PADW;         // [KC][PADW]  K chunk (k-major)
    float* sV   = sB + KC * PADW;         // [KC][PADW]  V chunk (row-major)
    float* sS   = sV + KC * PADW;         // [BM][PADW]  P tile, m-major: sS[m][n]
    float* sInv = sS + BM * PADW;         // [128]

    const float ww = w_w[h], bw = b_w[h], wb = w_b[h], bb = b_b[h];

    const float* qbase  = q   + ((size_t)bh * N_ + n0) * DH_;
    const float* kbase  = k   + (size_t)bh * N_ * DH_;
    const float* vbase  = v   + (size_t)bh * N_ * DH_;
    const float* dqbase = d_q + (size_t)b * N_ * 4;
    const float* dkbase = d_k + (size_t)b * N_ * 4;
    float* scbase = scores + ((size_t)bh * N_ + n0) * (size_t)N_;

    float o_acc[8][8];
    #pragma unroll
    for (int i = 0; i < 8; i++)
        #pragma unroll
        for (int j = 0; j < 8; j++) o_acc[i][j] = 0.0f;
    float rsum[8] = {0,0,0,0,0,0,0,0};

    // my 8 query rows' first-3 direction components + squared norms
    float dqx[8], dqy[8], dqz[8], sqq[8];
    #pragma unroll
    for (int i = 0; i < 8; i++){
        const int n = n0 + ty * 8 + i;
        const float4 dv = *(const float4*)(dqbase + (size_t)n * 4);
        dqx[i] = dv.x; dqy[i] = dv.y; dqz[i] = dv.z;
        sqq[i] = dv.x*dv.x + dv.y*dv.y + dv.z*dv.z;
    }

    for (int mt = 0; mt < N_ / BM; mt++){
        const int m0 = mt * BM;
        float s_acc[8][8];
        #pragma unroll
        for (int i = 0; i < 8; i++)
            #pragma unroll
            for (int j = 0; j < 8; j++) s_acc[i][j] = 0.0f;

        // ---- QK^T over DH in KC-chunks ----
        for (int kc = 0; kc < DH_ / KC; kc++){
            __syncthreads();
            #pragma unroll
            for (int sft = 0; sft < 2; sft++){
                const int idx = tid + sft * 256;
                const int row = idx >> 2;
                const int c4  = (idx & 3) * 4;
                const float4 qa = *(const float4*)(qbase + (size_t)row * DH_ + kc * KC + c4);
                sA[(c4 + 0) * PADW + row] = qa.x * SCALE_Q;
                sA[(c4 + 1) * PADW + row] = qa.y * SCALE_Q;
                sA[(c4 + 2) * PADW + row] = qa.z * SCALE_Q;
                sA[(c4 + 3) * PADW + row] = qa.w * SCALE_Q;
                const float4 kb = *(const float4*)(kbase + (size_t)(m0 + row) * DH_ + kc * KC + c4);
                sB[(c4 + 0) * PADW + row] = kb.x;
                sB[(c4 + 1) * PADW + row] = kb.y;
                sB[(c4 + 2) * PADW + row] = kb.z;
                sB[(c4 + 3) * PADW + row] = kb.w;
            }
            __syncthreads();
            #pragma unroll 4
            for (int kk = 0; kk < KC; kk++){
                const float4 a0 = *(const float4*)(sA + kk * PADW + ty * 8);
                const float4 a1 = *(const float4*)(sA + kk * PADW + ty * 8 + 4);
                const float4 b0 = *(const float4*)(sB + kk * PADW + tx * 8);
                const float4 b1 = *(const float4*)(sB + kk * PADW + tx * 8 + 4);
                const float af[8] = {a0.x,a0.y,a0.z,a0.w,a1.x,a1.y,a1.z,a1.w};
                const float bf[8] = {b0.x,b0.y,b0.z,b0.w,b1.x,b1.y,b1.z,b1.w};
                #pragma unroll
                for (int i = 0; i < 8; i++)
                    #pragma unroll
                    for (int j = 0; j < 8; j++)
                        s_acc[i][j] = fmaf(af[i], bf[j], s_acc[i][j]);
            }
        }

        // ---- distance map + relu, rowsum, write raw scores ----
        float dkx[8], dky[8], dkz[8], sqk[8];
        #pragma unroll
        for (int j = 0; j < 8; j++){
            const int m = m0 + tx * 8 + j;
            const float4 dv = *(const float4*)(dkbase + (size_t)m * 4);
            dkx[j] = dv.x; dky[j] = dv.y; dkz[j] = dv.z;
            sqk[j] = dv.x*dv.x + dv.y*dv.y + dv.z*dv.z;
        }
        #pragma unroll
        for (int i = 0; i < 8; i++){
            float row_s = 0.0f;
            #pragma unroll
            for (int j = 0; j < 8; j++){
                const float t3   = fmaf(dqx[i], dkx[j], fmaf(dqy[i], dky[j], dqz[i] * dkz[j]));
                const float dist = fmaf(-2.0f, t3, sqq[i] + sqk[j]);
                const float yw   = fmaf(dist, ww, bw);
                const float dmw  = softplus_neg_fast(yw);
                const float dmb  = fmaf(dist, wb, bb);
                float sv_ = fmaf(s_acc[i][j], dmw, dmb);
                sv_ = fmaxf(sv_, 0.0f);
                s_acc[i][j] = sv_;
                row_s += sv_;
            }
            rsum[i] += row_s;
        }
        #pragma unroll
        for (int i = 0; i < 8; i++){
            float4 w0, w1;
            w0.x = s_acc[i][0]; w0.y = s_acc[i][1]; w0.z = s_acc[i][2]; w0.w = s_acc[i][3];
            w1.x = s_acc[i][4]; w1.y = s_acc[i][5]; w1.z = s_acc[i][6]; w1.w = s_acc[i][7];
            float* sp = scbase + (size_t)(ty * 8 + i) * N_ + m0 + tx * 8;
            *(float4*)(sp)     = w0;
            *(float4*)(sp + 4) = w1;
        }
        #pragma unroll
        for (int j = 0; j < 8; j++)
            #pragma unroll
            for (int i = 0; i < 8; i++)
                sS[(tx * 8 + j) * PADW + ty * 8 + i] = s_acc[i][j];

        // ---- P @ V over this m-tile ----
        for (int vc = 0; vc < BM / KC; vc++){
            __syncthreads();
            #pragma unroll
            for (int sft = 0; sft < 2; sft++){
                const int idx = tid + sft * 256;
                const int row = idx >> 5;
                const int c4  = (idx & 31) * 4;
                const float4 vv = *(const float4*)(vbase + (size_t)(m0 + vc * KC + row) * DH_ + c4);
                *(float4*)(sV + row * PADW + c4) = vv;
            }
            __syncthreads();
            #pragma unroll 4
            for (int kk = 0; kk < KC; kk++){
                const float* srow = sS + (vc * KC + kk) * PADW;
                const float4 a0 = *(const float4*)(srow + ty * 8);
                const float4 a1 = *(const float4*)(srow + ty * 8 + 4);
                const float4 b0 = *(const float4*)(sV + kk * PADW + tx * 8);
                const float4 b1 = *(const float4*)(sV + kk * PADW + tx * 8 + 4);
                const float af[8] = {a0.x,a0.y,a0.z,a0.w,a1.x,a1.y,a1.z,a1.w};
                const float bf[8] = {b0.x,b0.y,b0.z,b0.w,b1.x,b1.y,b1.z,b1.w};
                #pragma unroll
                for (int i = 0; i < 8; i++)
                    #pragma unroll
                    for (int j = 0; j < 8; j++)
                        o_acc[i][j] = fmaf(af[i], bf[j], o_acc[i][j]);
            }
        }
    }

    // ---- row sums -> detr -> inverse; normalize out ----
    #pragma unroll
    for (int i = 0; i < 8; i++){
        float rv = rsum[i];
        rv += __shfl_xor_sync(0xffffffffu, rv, 1);
        rv += __shfl_xor_sync(0xffffffffu, rv, 2);
        rv += __shfl_xor_sync(0xffffffffu, rv, 4);
        rv += __shfl_xor_sync(0xffffffffu, rv, 8);
        rsum[i] = rv;
    }
    const float scv = g_sc[bh];
    __syncthreads();
    if (tx == 0){
        #pragma unroll
        for (int i = 0; i < 8; i++){
            const float detr = rsum[i] + scv + 1e-9f;
            const float invd = 1.0f / detr;
            sInv[ty * 8 + i] = invd;
            g_inv[(size_t)bh * N_ + n0 + ty * 8 + i] = invd;
        }
    }
    __syncthreads();
    float* obase = out + ((size_t)bh * N_ + n0) * DH_;
    #pragma unroll
    for (int i = 0; i < 8; i++){
        const float invd = sInv[ty * 8 + i];
        float4 w0, w1;
        w0.x = o_acc[i][0] * invd; w0.y = o_acc[i][1] * invd;
        w0.z = o_acc[i][2] * invd; w0.w = o_acc[i][3] * invd;
        w1.x = o_acc[i][4] * invd; w1.y = o_acc[i][5] * invd;
        w1.z = o_acc[i][6] * invd; w1.w = o_acc[i][7] * invd;
        float* op = obase + (size_t)(ty * 8 + i) * DH_ + tx * 8;
        *(float4*)(op)     = w0;
        *(float4*)(op + 4) = w1;
    }
}

// ---- in-place normalization of the scores tensor ----
__global__ void k_scale(float* __restrict__ scores){
    const size_t total4 = (size_t)BH_ * N_ * N_ / 4;
    const size_t stride = (size_t)gridDim.x * blockDim.x;
    float4* p = (float4*)scores;
    for (size_t i = (size_t)blockIdx.x * blockDim.x + threadIdx.x; i < total4; i += stride){
        const size_t row = i >> 8;          // N_/4 = 256 float4 per row
        const float invd = g_inv[row];
        float4 x = p[i];
        x.x *= invd; x.y *= invd; x.z *= invd; x.w *= invd;
        p[i] = x;
    }
}

extern "C" void kernel_launch(void* const* d_in, const int* in_sizes, int n_in,
                              void* d_out, int out_size)
{
    const float* q  = (const float*)d_in[0];
    const float* k  = (const float*)d_in[1];
    const float* v  = (const float*)d_in[2];
    const float* c  = (const float*)d_in[3];
    const float* dq = (const float*)d_in[4];
    const float* dk = (const float*)d_in[5];
    const float* ww = (const float*)d_in[6];
    const float* bw = (const float*)d_in[7];
    const float* wb = (const float*)d_in[8];
    const float* bb = (const float*)d_in[9];

    float* out    = (float*)d_out;
    float* scores = out + (size_t)BH_ * N_ * DH_;

    const int smem_bytes = (3 * KC * PADW + BM * PADW + 128) * (int)sizeof(float);
    cudaFuncSetAttribute(k_main, cudaFuncAttributeMaxDynamicSharedMemorySize, smem_bytes);

    k_sc<<<BH_, 256>>>(c);
    k_main<<<BH_ * (N_ / BM), 256, smem_bytes>>>(q, k, v, dq, dk, ww, bw, wb, bb, out, scores);
    k_scale<<<8192, 256>>>(scores);
}

// round 6
// speedup vs baseline: 1.7167x; 1.7167x over previous
#include <cuda_runtime.h>
#include <cuda_bf16.h>
#include <math.h>
#include <stdint.h>

#define B_  4
#define H_  8
#define N_  1024
#define DH_ 128
#define BH_ (B_*H_)
#define BM  128
#define MT  128
#define NTILES (N_/MT)
#define SCALE_Q 0.08838834764831845f  /* 1/sqrt(128) */

// ---------------- smem layout (bytes) ----------------
#define OFF_QH   0
#define OFF_QL   32768
#define OFF_KVH  65536
#define OFF_KVL  98304
#define OFF_PH   131072
#define OFF_PL   163840
#define OFF_DK   196608              /* float4[128] = 2048 */
#define OFF_RS   198656              /* float[256]  = 1024 */
#define OFF_INV  199680              /* float[128]  = 512  */
#define SMEM_TOTAL 200192

__device__ float g_sc[BH_];
__device__ float g_inv[BH_*N_];

// ---------------- helpers ----------------
__device__ __forceinline__ uint32_t smem_u32(const void* p){
    uint32_t a;
    asm("{ .reg .u64 t; cvta.to.shared.u64 t, %1; cvt.u32.u64 %0, t; }" : "=r"(a) : "l"(p));
    return a;
}
__device__ __forceinline__ void ldsm4(uint32_t* r, uint32_t addr){
    asm volatile("ldmatrix.sync.aligned.m8n8.x4.shared.b16 {%0,%1,%2,%3}, [%4];"
        : "=r"(r[0]), "=r"(r[1]), "=r"(r[2]), "=r"(r[3]) : "r"(addr));
}
__device__ __forceinline__ void ldsm4t(uint32_t* r, uint32_t addr){
    asm volatile("ldmatrix.sync.aligned.m8n8.x4.trans.shared.b16 {%0,%1,%2,%3}, [%4];"
        : "=r"(r[0]), "=r"(r[1]), "=r"(r[2]), "=r"(r[3]) : "r"(addr));
}
__device__ __forceinline__ void mma16816(float* c, const uint32_t* a, const uint32_t* b){
    asm volatile("mma.sync.aligned.m16n8k16.row.col.f32.bf16.bf16.f32 "
        "{%0,%1,%2,%3}, {%4,%5,%6,%7}, {%8,%9}, {%0,%1,%2,%3};"
        : "+f"(c[0]), "+f"(c[1]), "+f"(c[2]), "+f"(c[3])
        : "r"(a[0]), "r"(a[1]), "r"(a[2]), "r"(a[3]), "r"(b[0]), "r"(b[1]));
}

// swizzled byte offset in a 128x128 bf16 tile (2 atom-cols of 64, SW128 per 128B row)
__device__ __forceinline__ int swzel(int row, int col){
    return ((col >> 6) << 14) + ((row >> 3) << 10) + ((row & 7) << 7)
         + ((((col & 63) << 1)) ^ ((row & 7) << 4));
}
__device__ __forceinline__ int swz4(int row, int c4){ return swzel(row, c4); }

__device__ __forceinline__ uint32_t bf2u(__nv_bfloat162 x){ return *reinterpret_cast<uint32_t*>(&x); }

__device__ __forceinline__ void split_store4(char* ph, char* pl, float4 v){
    __nv_bfloat162 h01 = __floats2bfloat162_rn(v.x, v.y);
    __nv_bfloat162 h23 = __floats2bfloat162_rn(v.z, v.w);
    float l0 = v.x - __bfloat162float(h01.x);
    float l1 = v.y - __bfloat162float(h01.y);
    float l2 = v.z - __bfloat162float(h23.x);
    float l3 = v.w - __bfloat162float(h23.y);
    __nv_bfloat162 q01 = __floats2bfloat162_rn(l0, l1);
    __nv_bfloat162 q23 = __floats2bfloat162_rn(l2, l3);
    *(uint2*)ph = make_uint2(bf2u(h01), bf2u(h23));
    *(uint2*)pl = make_uint2(bf2u(q01), bf2u(q23));
}

// one 3-pass gemm slab: acc[2][8][4] covers rows wm32..+31 x cols nb64..+63
template<bool BT>
__device__ __forceinline__ void gemm_pass(uint32_t aT, uint32_t bT,
        float (&acc)[2][8][4], int lane, int wm32, int nb64)
{
    #pragma unroll
    for (int ks = 0; ks < 8; ks++){
        const int kc = ks * 16;
        uint32_t a0[4], a1[4];
        ldsm4(a0, aT + swzel(wm32 +      (lane & 15), kc + ((lane >> 4) << 3)));
        ldsm4(a1, aT + swzel(wm32 + 16 + (lane & 15), kc + ((lane >> 4) << 3)));
        uint32_t bb[4][4];
        #pragma unroll
        for (int blk = 0; blk < 4; blk++){
            if (BT){
                // B stored [m][d] (rows = k), transpose in LDSM
                ldsm4t(bb[blk], bT + swzel(kc + (((lane >> 4) & 1) << 3) + (lane & 7),
                                           nb64 + blk * 16 + (((lane >> 3) & 1) << 3)));
            } else {
                // B stored [n][k] (K-major)
                ldsm4(bb[blk], bT + swzel(nb64 + blk * 16 + (lane & 7) + (((lane >> 3) & 1) << 3),
                                          kc + ((lane >> 4) << 3)));
            }
        }
        #pragma unroll
        for (int fn = 0; fn < 8; fn++){
            uint32_t b2[2] = { bb[fn >> 1][fn & 1], bb[fn >> 1][2 + (fn & 1)] };
            mma16816(acc[0][fn], a0, b2);
            mma16816(acc[1][fn], a1, b2);
        }
    }
}

// ---------------- kernel A: per-(b,h) sum softplus(c) ----------------
__global__ void k_sc(const float* __restrict__ c){
    const int bh = blockIdx.x, tid = threadIdx.x;
    const float* cp = c + (size_t)bh * N_;
    float s = 0.0f;
    for (int i = tid; i < N_; i += 256){
        float x = cp[i];
        s += fmaxf(x, 0.0f) + log1pf(__expf(-fabsf(x)));
    }
    #pragma unroll
    for (int o = 16; o; o >>= 1) s += __shfl_xor_sync(0xffffffffu, s, o);
    __shared__ float red[8];
    if ((tid & 31) == 0) red[tid >> 5] = s;
    __syncthreads();
    if (tid == 0){
        float t = 0.0f;
        #pragma unroll
        for (int i = 0; i < 8; i++) t += red[i];
        g_sc[bh] = t;
    }
}

// ---------------- main tensor-core kernel ----------------
extern __shared__ __align__(16) char smem[];

__global__ __launch_bounds__(256)
void k_main(const float* __restrict__ q, const float* __restrict__ k,
            const float* __restrict__ v, const float* __restrict__ d_q,
            const float* __restrict__ d_k,
            const float* __restrict__ w_w, const float* __restrict__ b_w,
            const float* __restrict__ w_b, const float* __restrict__ b_b,
            float* __restrict__ out, float* __restrict__ scores)
{
    const int tid  = threadIdx.x;
    const int w    = tid >> 5, lane = tid & 31;
    const int g    = lane >> 2, t = lane & 3;
    const int bh   = blockIdx.x >> 3, rt = blockIdx.x & 7;
    const int b    = bh >> 3, h = bh & 7;
    const int n0   = rt * BM;
    const int wm32 = (w & 3) * 32;
    const int wn   = w >> 2;
    const int nb64 = wn * 64;

    const uint32_t sb  = smem_u32(smem);
    const uint32_t sQH = sb + OFF_QH,  sQL = sb + OFF_QL;
    const uint32_t sKH = sb + OFF_KVH, sKL = sb + OFF_KVL;
    const uint32_t sPH = sb + OFF_PH,  sPL = sb + OFF_PL;

    const float* qbase = q + ((size_t)bh * N_ + n0) * DH_;
    const float* kbase = k + (size_t)bh * N_ * DH_;
    const float* vbase = v + (size_t)bh * N_ * DH_;
    float* scbase = scores + ((size_t)bh * N_ + n0) * (size_t)N_;

    // ---- load + split Q (pre-scaled) ----
    #pragma unroll 4
    for (int it = 0; it < 16; it++){
        int idx = it * 256 + tid;
        int row = idx >> 5, c4 = (idx & 31) * 4;
        float4 qa = *(const float4*)(qbase + (size_t)row * DH_ + c4);
        qa.x *= SCALE_Q; qa.y *= SCALE_Q; qa.z *= SCALE_Q; qa.w *= SCALE_Q;
        int off = swz4(row, c4);
        split_store4(smem + OFF_QH + off, smem + OFF_QL + off, qa);
    }

    // ---- per-lane row constants (4 rows: fm x rowhalf) ----
    const float ww = w_w[h], bw = b_w[h], wb = w_b[h], bb = b_b[h];
    const float m2w = -2.0f * ww, m2b = -2.0f * wb;
    float dqx_[2][2], dqy_[2][2], dqz_[2][2], aq_[2][2], ab_[2][2];
    #pragma unroll
    for (int fm = 0; fm < 2; fm++)
        #pragma unroll
        for (int rh = 0; rh < 2; rh++){
            int r = wm32 + fm * 16 + rh * 8 + g;
            float4 dv = *(const float4*)(d_q + ((size_t)b * N_ + n0 + r) * 4);
            dqx_[fm][rh] = dv.x; dqy_[fm][rh] = dv.y; dqz_[fm][rh] = dv.z;
            float sq = dv.x*dv.x + dv.y*dv.y + dv.z*dv.z;
            aq_[fm][rh] = fmaf(ww, sq, bw);
            ab_[fm][rh] = fmaf(wb, sq, bb);
        }

    float o_acc[2][8][4];
    #pragma unroll
    for (int fm = 0; fm < 2; fm++)
        #pragma unroll
        for (int fn = 0; fn < 8; fn++)
            #pragma unroll
            for (int e = 0; e < 4; e++) o_acc[fm][fn][e] = 0.0f;
    float rs_[2][2] = {{0.0f,0.0f},{0.0f,0.0f}};

    for (int mt = 0; mt < NTILES; mt++){
        const int m0 = mt * MT;
        __syncthreads();   // previous PV done reading KV

        // ---- load + split K tile (K-major [n][k]) + dk ----
        #pragma unroll 4
        for (int it = 0; it < 16; it++){
            int idx = it * 256 + tid;
            int row = idx >> 5, c4 = (idx & 31) * 4;
            float4 kv = *(const float4*)(kbase + (size_t)(m0 + row) * DH_ + c4);
            int off = swz4(row, c4);
            split_store4(smem + OFF_KVH + off, smem + OFF_KVL + off, kv);
        }
        if (tid < 128){
            float4 dv = *(const float4*)(d_k + ((size_t)b * N_ + m0 + tid) * 4);
            ((float4*)(smem + OFF_DK))[tid] =
                make_float4(dv.x, dv.y, dv.z, dv.x*dv.x + dv.y*dv.y + dv.z*dv.z);
        }
        __syncthreads();

        // ---- S = Q K^T, 3-pass bf16 split ----
        float s_acc[2][8][4];
        #pragma unroll
        for (int fm = 0; fm < 2; fm++)
            #pragma unroll
            for (int fn = 0; fn < 8; fn++)
                #pragma unroll
                for (int e = 0; e < 4; e++) s_acc[fm][fn][e] = 0.0f;
        gemm_pass<false>(sQH, sKH, s_acc, lane, wm32, nb64);
        gemm_pass<false>(sQL, sKH, s_acc, lane, wm32, nb64);
        gemm_pass<false>(sQH, sKL, s_acc, lane, wm32, nb64);

        // ---- map epilogue: dist map + relu, rowsum, scores out, P->smem ----
        const float4* dk4s = (const float4*)(smem + OFF_DK);
        #pragma unroll
        for (int fm = 0; fm < 2; fm++){
            #pragma unroll
            for (int fn = 0; fn < 8; fn++){
                const int c0 = nb64 + fn * 8 + t * 2;
                const float4 dA = dk4s[c0];
                const float4 dB = dk4s[c0 + 1];
                float p[4];
                #pragma unroll
                for (int e = 0; e < 4; e++){
                    const int rh = e >> 1;
                    const float4 dk = (e & 1) ? dB : dA;
                    float t3 = fmaf(dqx_[fm][rh], dk.x,
                               fmaf(dqy_[fm][rh], dk.y, dqz_[fm][rh] * dk.z));
                    float yw = fmaf(m2w, t3, fmaf(ww, dk.w, aq_[fm][rh]));
                    float db = fmaf(m2b, t3, fmaf(wb, dk.w, ab_[fm][rh]));
                    float z  = fmaxf(fabsf(yw) * -1.4426950408889634f, -126.0f);
                    float ex; asm("ex2.approx.f32 %0, %1;" : "=f"(ex) : "f"(z));
                    float lg; asm("lg2.approx.f32 %0, %1;" : "=f"(lg) : "f"(1.0f + ex));
                    float sp = fmaf(0.6931471805599453f, lg, fmaxf(-yw, 0.0f));
                    float pv = fmaf(s_acc[fm][fn][e], sp, db);
                    pv = fmaxf(pv, 0.0f);
                    p[e] = pv;
                    rs_[fm][rh] += pv;
                }
                const int r0 = wm32 + fm * 16 + g, r1 = r0 + 8;
                *(float2*)(scbase + (size_t)r0 * N_ + m0 + c0) = make_float2(p[0], p[1]);
                *(float2*)(scbase + (size_t)r1 * N_ + m0 + c0) = make_float2(p[2], p[3]);
                {
                    __nv_bfloat162 h0 = __floats2bfloat162_rn(p[0], p[1]);
                    __nv_bfloat162 l0 = __floats2bfloat162_rn(
                        p[0] - __bfloat162float(h0.x), p[1] - __bfloat162float(h0.y));
                    int off0 = swzel(r0, c0);
                    *(uint32_t*)(smem + OFF_PH + off0) = bf2u(h0);
                    *(uint32_t*)(smem + OFF_PL + off0) = bf2u(l0);
                    __nv_bfloat162 h1 = __floats2bfloat162_rn(p[2], p[3]);
                    __nv_bfloat162 l1 = __floats2bfloat162_rn(
                        p[2] - __bfloat162float(h1.x), p[3] - __bfloat162float(h1.y));
                    int off1 = swzel(r1, c0);
                    *(uint32_t*)(smem + OFF_PH + off1) = bf2u(h1);
                    *(uint32_t*)(smem + OFF_PL + off1) = bf2u(l1);
                }
            }
        }
        __syncthreads();   // P complete; all warps done reading K from KV

        // ---- load + split V tile (natural [m][d] layout) ----
        #pragma unroll 4
        for (int it = 0; it < 16; it++){
            int idx = it * 256 + tid;
            int row = idx >> 5, c4 = (idx & 31) * 4;
            float4 vv = *(const float4*)(vbase + (size_t)(m0 + row) * DH_ + c4);
            int off = swz4(row, c4);
            split_store4(smem + OFF_KVH + off, smem + OFF_KVL + off, vv);
        }
        __syncthreads();

        // ---- O += P V, 3-pass bf16 split (B transposed in LDSM) ----
        gemm_pass<true>(sPH, sKH, o_acc, lane, wm32, nb64);
        gemm_pass<true>(sPL, sKH, o_acc, lane, wm32, nb64);
        gemm_pass<true>(sPH, sKL, o_acc, lane, wm32, nb64);
    }

    // ---- rowsum reduce -> detr -> inverse ----
    float* RS = (float*)(smem + OFF_RS);
    #pragma unroll
    for (int fm = 0; fm < 2; fm++)
        #pragma unroll
        for (int rh = 0; rh < 2; rh++){
            float vsum = rs_[fm][rh];
            vsum += __shfl_xor_sync(0xffffffffu, vsum, 1);
            vsum += __shfl_xor_sync(0xffffffffu, vsum, 2);
            if (t == 0) RS[wn * 128 + wm32 + fm * 16 + rh * 8 + g] = vsum;
        }
    __syncthreads();
    if (tid < 128){
        float detr = RS[tid] + RS[128 + tid] + g_sc[bh] + 1e-9f;
        float inv = 1.0f / detr;
        ((float*)(smem + OFF_INV))[tid] = inv;
        g_inv[(size_t)bh * N_ + n0 + tid] = inv;
    }
    __syncthreads();

    // ---- write O (normalized) ----
    const float* INV = (const float*)(smem + OFF_INV);
    #pragma unroll
    for (int fm = 0; fm < 2; fm++){
        const int r0 = wm32 + fm * 16 + g, r1 = r0 + 8;
        const float i0 = INV[r0], i1 = INV[r1];
        float* ob0 = out + ((size_t)bh * N_ + n0 + r0) * DH_;
        float* ob1 = out + ((size_t)bh * N_ + n0 + r1) * DH_;
        #pragma unroll
        for (int fn = 0; fn < 8; fn++){
            const int c0 = nb64 + fn * 8 + t * 2;
            *(float2*)(ob0 + c0) = make_float2(o_acc[fm][fn][0] * i0, o_acc[fm][fn][1] * i0);
            *(float2*)(ob1 + c0) = make_float2(o_acc[fm][fn][2] * i1, o_acc[fm][fn][3] * i1);
        }
    }
}

// ---------------- scores normalization ----------------
__global__ void k_scale(float* __restrict__ scores){
    const size_t total4 = (size_t)BH_ * N_ * N_ / 4;
    const size_t stride = (size_t)gridDim.x * blockDim.x;
    float4* p = (float4*)scores;
    for (size_t i = (size_t)blockIdx.x * blockDim.x + threadIdx.x; i < total4; i += stride){
        const size_t row = i >> 8;
        const float invd = g_inv[row];
        float4 x = p[i];
        x.x *= invd; x.y *= invd; x.z *= invd; x.w *= invd;
        p[i] = x;
    }
}

extern "C" void kernel_launch(void* const* d_in, const int* in_sizes, int n_in,
                              void* d_out, int out_size)
{
    const float* q  = (const float*)d_in[0];
    const float* k  = (const float*)d_in[1];
    const float* v  = (const float*)d_in[2];
    const float* c  = (const float*)d_in[3];
    const float* dq = (const float*)d_in[4];
    const float* dk = (const float*)d_in[5];
    const float* ww = (const float*)d_in[6];
    const float* bw = (const float*)d_in[7];
    const float* wb = (const float*)d_in[8];
    const float* bb = (const float*)d_in[9];

    float* out    = (float*)d_out;
    float* scores = out + (size_t)BH_ * N_ * DH_;

    cudaFuncSetAttribute(k_main, cudaFuncAttributeMaxDynamicSharedMemorySize, SMEM_TOTAL);

    k_sc<<<BH_, 256>>>(c);
    k_main<<<BH_ * (N_ / BM), 256, SMEM_TOTAL>>>(q, k, v, dq, dk, ww, bw, wb, bb, out, scores);
    k_scale<<<8192, 256>>>(scores);
}

// round 8
// speedup vs baseline: 1.9951x; 1.1622x over previous
#include <cuda_runtime.h>
#include <cuda_bf16.h>
#include <math.h>
#include <stdint.h>

#define B_  4
#define H_  8
#define N_  1024
#define DH_ 128
#define BH_ (B_*H_)
#define BM  128
#define MT  128
#define NTILES (N_/MT)
#define SCALE_Q 0.08838834764831845f  /* 1/sqrt(128) */

// ---------------- smem layout (bytes) ----------------
#define OFF_QH   0
#define OFF_QL   32768
#define OFF_KH   65536
#define OFF_KL   98304
#define OFF_VH   131072
#define OFF_VL   163840
#define OFF_DK   196608              /* float4[128] = 2048 */
#define OFF_RS   198656              /* float[256]  = 1024 */
#define OFF_INV  199680              /* float[128]  = 512  */
#define SMEM_TOTAL 200192
/* O-reduction scratch reuses OFF_QH (64KB, dead after last QK) */

__device__ float g_sc[BH_];
__device__ float g_inv[BH_*N_];

// ---------------- helpers ----------------
__device__ __forceinline__ uint32_t smem_u32(const void* p){
    uint32_t a;
    asm("{ .reg .u64 t; cvta.to.shared.u64 t, %1; cvt.u32.u64 %0, t; }" : "=r"(a) : "l"(p));
    return a;
}
__device__ __forceinline__ void ldsm4(uint32_t* r, uint32_t addr){
    asm volatile("ldmatrix.sync.aligned.m8n8.x4.shared.b16 {%0,%1,%2,%3}, [%4];"
        : "=r"(r[0]), "=r"(r[1]), "=r"(r[2]), "=r"(r[3]) : "r"(addr));
}
__device__ __forceinline__ void ldsm4t(uint32_t* r, uint32_t addr){
    asm volatile("ldmatrix.sync.aligned.m8n8.x4.trans.shared.b16 {%0,%1,%2,%3}, [%4];"
        : "=r"(r[0]), "=r"(r[1]), "=r"(r[2]), "=r"(r[3]) : "r"(addr));
}
__device__ __forceinline__ void mma16816(float* c, const uint32_t* a, const uint32_t* b){
    asm volatile("mma.sync.aligned.m16n8k16.row.col.f32.bf16.bf16.f32 "
        "{%0,%1,%2,%3}, {%4,%5,%6,%7}, {%8,%9}, {%0,%1,%2,%3};"
        : "+f"(c[0]), "+f"(c[1]), "+f"(c[2]), "+f"(c[3])
        : "r"(a[0]), "r"(a[1]), "r"(a[2]), "r"(a[3]), "r"(b[0]), "r"(b[1]));
}

// swizzled byte offset in a 128x128 bf16 tile (2 atom-cols of 64, SW128 per 128B row)
__device__ __forceinline__ int swzel(int row, int col){
    return ((col >> 6) << 14) + ((row >> 3) << 10) + ((row & 7) << 7)
         + ((((col & 63) << 1)) ^ ((row & 7) << 4));
}

__device__ __forceinline__ uint32_t bf2u(__nv_bfloat162 x){ return *reinterpret_cast<uint32_t*>(&x); }

__device__ __forceinline__ void split_store4(char* ph, char* pl, float4 v){
    __nv_bfloat162 h01 = __floats2bfloat162_rn(v.x, v.y);
    __nv_bfloat162 h23 = __floats2bfloat162_rn(v.z, v.w);
    float l0 = v.x - __bfloat162float(h01.x);
    float l1 = v.y - __bfloat162float(h01.y);
    float l2 = v.z - __bfloat162float(h23.x);
    float l3 = v.w - __bfloat162float(h23.y);
    __nv_bfloat162 q01 = __floats2bfloat162_rn(l0, l1);
    __nv_bfloat162 q23 = __floats2bfloat162_rn(l2, l3);
    *(uint2*)ph = make_uint2(bf2u(h01), bf2u(h23));
    *(uint2*)pl = make_uint2(bf2u(q01), bf2u(q23));
}

// ---------------- kernel A: per-(b,h) sum softplus(c) ----------------
__global__ void k_sc(const float* __restrict__ c){
    const int bh = blockIdx.x, tid = threadIdx.x;
    const float* cp = c + (size_t)bh * N_;
    float s = 0.0f;
    for (int i = tid; i < N_; i += 256){
        float x = cp[i];
        s += fmaxf(x, 0.0f) + log1pf(__expf(-fabsf(x)));
    }
    #pragma unroll
    for (int o = 16; o; o >>= 1) s += __shfl_xor_sync(0xffffffffu, s, o);
    __shared__ float red[8];
    if ((tid & 31) == 0) red[tid >> 5] = s;
    __syncthreads();
    if (tid == 0){
        float t = 0.0f;
        #pragma unroll
        for (int i = 0; i < 8; i++) t += red[i];
        g_sc[bh] = t;
    }
}

// ---------------- main tensor-core kernel ----------------
extern __shared__ __align__(16) char smem[];

__global__ __launch_bounds__(256)
void k_main(const float* __restrict__ q, const float* __restrict__ k,
            const float* __restrict__ v, const float* __restrict__ d_q,
            const float* __restrict__ d_k,
            const float* __restrict__ w_w, const float* __restrict__ b_w,
            const float* __restrict__ w_b, const float* __restrict__ b_b,
            float* __restrict__ out, float* __restrict__ scores)
{
    const int tid  = threadIdx.x;
    const int w    = tid >> 5, lane = tid & 31;
    const int g    = lane >> 2, t = lane & 3;
    const int bh   = blockIdx.x >> 3, rt = blockIdx.x & 7;
    const int b    = bh >> 3, h = bh & 7;
    const int n0   = rt * BM;
    const int wm32 = (w & 3) * 32;
    const int wn   = w >> 2;
    const int nb64 = wn * 64;

    const uint32_t sb  = smem_u32(smem);
    const uint32_t sQH = sb + OFF_QH, sQL = sb + OFF_QL;
    const uint32_t sKH = sb + OFF_KH, sKL = sb + OFF_KL;
    const uint32_t sVH = sb + OFF_VH, sVL = sb + OFF_VL;

    const float* qbase = q + ((size_t)bh * N_ + n0) * DH_;
    const float* kbase = k + (size_t)bh * N_ * DH_;
    const float* vbase = v + (size_t)bh * N_ * DH_;
    float* scbase = scores + ((size_t)bh * N_ + n0) * (size_t)N_;

    // ---- load + split Q (pre-scaled) ----
    #pragma unroll 4
    for (int it = 0; it < 16; it++){
        int idx = it * 256 + tid;
        int row = idx >> 5, c4 = (idx & 31) * 4;
        float4 qa = *(const float4*)(qbase + (size_t)row * DH_ + c4);
        qa.x *= SCALE_Q; qa.y *= SCALE_Q; qa.z *= SCALE_Q; qa.w *= SCALE_Q;
        int off = swzel(row, c4);
        split_store4(smem + OFF_QH + off, smem + OFF_QL + off, qa);
    }

    // ---- per-lane row constants (4 rows: fm x rowhalf) ----
    const float ww = w_w[h], bw = b_w[h], wb = w_b[h], bb = b_b[h];
    const float m2w = -2.0f * ww, m2b = -2.0f * wb;
    float dqx_[2][2], dqy_[2][2], dqz_[2][2], aq_[2][2], ab_[2][2];
    #pragma unroll
    for (int fm = 0; fm < 2; fm++)
        #pragma unroll
        for (int rh = 0; rh < 2; rh++){
            int r = wm32 + fm * 16 + rh * 8 + g;
            float4 dv = *(const float4*)(d_q + ((size_t)b * N_ + n0 + r) * 4);
            dqx_[fm][rh] = dv.x; dqy_[fm][rh] = dv.y; dqz_[fm][rh] = dv.z;
            float sq = dv.x*dv.x + dv.y*dv.y + dv.z*dv.z;
            aq_[fm][rh] = fmaf(ww, sq, bw);
            ab_[fm][rh] = fmaf(wb, sq, bb);
        }

    // O accumulator: full d=128 per warp, k restricted to this warp's 64-col slab
    float o_acc[2][16][4];
    #pragma unroll
    for (int fm = 0; fm < 2; fm++)
        #pragma unroll
        for (int fn = 0; fn < 16; fn++)
            #pragma unroll
            for (int e = 0; e < 4; e++) o_acc[fm][fn][e] = 0.0f;
    float rs_[2][2] = {{0.0f,0.0f},{0.0f,0.0f}};

    const int aRowOff = (lane & 15), aColOff = ((lane >> 4) << 3);
    const int bRowOff = (lane & 7) + (((lane >> 3) & 1) << 3), bColOff = ((lane >> 4) << 3);
    const int vtRow = (((lane >> 4) & 1) << 3) + (lane & 7), vtCol = (((lane >> 3) & 1) << 3);

    for (int mt = 0; mt < NTILES; mt++){
        const int m0 = mt * MT;
        __syncthreads();   // prior tile's MMAs done reading K/V smem

        // ---- load + split K and V tiles (concurrent LDG streams) + dk ----
        #pragma unroll 2
        for (int it = 0; it < 16; it++){
            int idx = it * 256 + tid;
            int row = idx >> 5, c4 = (idx & 31) * 4;
            float4 kv = *(const float4*)(kbase + (size_t)(m0 + row) * DH_ + c4);
            float4 vv = *(const float4*)(vbase + (size_t)(m0 + row) * DH_ + c4);
            int off = swzel(row, c4);
            split_store4(smem + OFF_KH + off, smem + OFF_KL + off, kv);
            split_store4(smem + OFF_VH + off, smem + OFF_VL + off, vv);
        }
        if (tid < 128){
            float4 dv = *(const float4*)(d_k + ((size_t)b * N_ + m0 + tid) * 4);
            ((float4*)(smem + OFF_DK))[tid] =
                make_float4(dv.x, dv.y, dv.z, dv.x*dv.x + dv.y*dv.y + dv.z*dv.z);
        }
        __syncthreads();

        // ---- S = Q K^T, 3-pass bf16 split, fragment-reuse schedule ----
        float s_acc[2][8][4];
        #pragma unroll
        for (int fm = 0; fm < 2; fm++)
            #pragma unroll
            for (int fn = 0; fn < 8; fn++)
                #pragma unroll
                for (int e = 0; e < 4; e++) s_acc[fm][fn][e] = 0.0f;

        #pragma unroll
        for (int ks = 0; ks < 8; ks++){
            const int kc = ks * 16;
            uint32_t aqh0[4], aqh1[4], aql0[4], aql1[4];
            ldsm4(aqh0, sQH + swzel(wm32 +      aRowOff, kc + aColOff));
            ldsm4(aqh1, sQH + swzel(wm32 + 16 + aRowOff, kc + aColOff));
            ldsm4(aql0, sQL + swzel(wm32 +      aRowOff, kc + aColOff));
            ldsm4(aql1, sQL + swzel(wm32 + 16 + aRowOff, kc + aColOff));
            #pragma unroll
            for (int blk = 0; blk < 4; blk++){
                uint32_t bkh[4], bkl[4];
                ldsm4(bkh, sKH + swzel(nb64 + blk * 16 + bRowOff, kc + bColOff));
                #pragma unroll
                for (int sub = 0; sub < 2; sub++){
                    uint32_t b2[2] = { bkh[sub], bkh[2 + sub] };
                    mma16816(s_acc[0][blk*2+sub], aqh0, b2);
                    mma16816(s_acc[1][blk*2+sub], aqh1, b2);
                    mma16816(s_acc[0][blk*2+sub], aql0, b2);
                    mma16816(s_acc[1][blk*2+sub], aql1, b2);
                }
                ldsm4(bkl, sKL + swzel(nb64 + blk * 16 + bRowOff, kc + bColOff));
                #pragma unroll
                for (int sub = 0; sub < 2; sub++){
                    uint32_t b2[2] = { bkl[sub], bkl[2 + sub] };
                    mma16816(s_acc[0][blk*2+sub], aqh0, b2);
                    mma16816(s_acc[1][blk*2+sub], aqh1, b2);
                }
            }
        }

        // ---- map epilogue: dist map + relu, rowsum, scores out, pack P A-frags ----
        uint32_t pah[2][4][4], pal[2][4][4];
        const float4* dk4s = (const float4*)(smem + OFF_DK);
        #pragma unroll
        for (int fm = 0; fm < 2; fm++){
            #pragma unroll
            for (int fn = 0; fn < 8; fn++){
                const int c0 = nb64 + fn * 8 + t * 2;
                const float4 dA = dk4s[c0];
                const float4 dB = dk4s[c0 + 1];
                float p[4];
                #pragma unroll
                for (int e = 0; e < 4; e++){
                    const int rh = e >> 1;
                    const float4 dk = (e & 1) ? dB : dA;
                    float t3 = fmaf(dqx_[fm][rh], dk.x,
                               fmaf(dqy_[fm][rh], dk.y, dqz_[fm][rh] * dk.z));
                    float yw = fmaf(m2w, t3, fmaf(ww, dk.w, aq_[fm][rh]));
                    float db = fmaf(m2b, t3, fmaf(wb, dk.w, ab_[fm][rh]));
                    float z  = fmaxf(fabsf(yw) * -1.4426950408889634f, -126.0f);
                    float ex; asm("ex2.approx.f32 %0, %1;" : "=f"(ex) : "f"(z));
                    float lg; asm("lg2.approx.f32 %0, %1;" : "=f"(lg) : "f"(1.0f + ex));
                    float sp = fmaf(0.6931471805599453f, lg, fmaxf(-yw, 0.0f));
                    float pv = fmaf(s_acc[fm][fn][e], sp, db);
                    pv = fmaxf(pv, 0.0f);
                    p[e] = pv;
                    rs_[fm][rh] += pv;
                }
                const int r0 = wm32 + fm * 16 + g, r1 = r0 + 8;
                *(float2*)(scbase + (size_t)r0 * N_ + m0 + c0) = make_float2(p[0], p[1]);
                *(float2*)(scbase + (size_t)r1 * N_ + m0 + c0) = make_float2(p[2], p[3]);
                // pack C-frag -> A-frag (registers), hi + lo split
                const int kb = fn >> 1, base = (fn & 1) * 2;
                __nv_bfloat162 h01 = __floats2bfloat162_rn(p[0], p[1]);
                __nv_bfloat162 h23 = __floats2bfloat162_rn(p[2], p[3]);
                pah[fm][kb][base + 0] = bf2u(h01);
                pah[fm][kb][base + 1] = bf2u(h23);
                __nv_bfloat162 l01 = __floats2bfloat162_rn(
                    p[0] - __bfloat162float(h01.x), p[1] - __bfloat162float(h01.y));
                __nv_bfloat162 l23 = __floats2bfloat162_rn(
                    p[2] - __bfloat162float(h23.x), p[3] - __bfloat162float(h23.y));
                pal[fm][kb][base + 0] = bf2u(l01);
                pal[fm][kb][base + 1] = bf2u(l23);
            }
        }

        // ---- O += P V (A from registers; k = this warp's 64-col slab) ----
        #pragma unroll
        for (int ks = 0; ks < 4; ks++){
            const int krow = nb64 + ks * 16;
            #pragma unroll
            for (int blk = 0; blk < 8; blk++){
                uint32_t bvh[4], bvl[4];
                ldsm4t(bvh, sVH + swzel(krow + vtRow, blk * 16 + vtCol));
                #pragma unroll
                for (int sub = 0; sub < 2; sub++){
                    uint32_t b2[2] = { bvh[sub], bvh[2 + sub] };
                    mma16816(o_acc[0][blk*2+sub], pah[0][ks], b2);
                    mma16816(o_acc[1][blk*2+sub], pah[1][ks], b2);
                    mma16816(o_acc[0][blk*2+sub], pal[0][ks], b2);
                    mma16816(o_acc[1][blk*2+sub], pal[1][ks], b2);
                }
                ldsm4t(bvl, sVL + swzel(krow + vtRow, blk * 16 + vtCol));
                #pragma unroll
                for (int sub = 0; sub < 2; sub++){
                    uint32_t b2[2] = { bvl[sub], bvl[2 + sub] };
                    mma16816(o_acc[0][blk*2+sub], pah[0][ks], b2);
                    mma16816(o_acc[1][blk*2+sub], pah[1][ks], b2);
                }
            }
        }
    }

    // ---- rowsum reduce; wn=1 stages O partial into (dead) Q smem ----
    float* RS = (float*)(smem + OFF_RS);
    #pragma unroll
    for (int fm = 0; fm < 2; fm++)
        #pragma unroll
        for (int rh = 0; rh < 2; rh++){
            float vsum = rs_[fm][rh];
            vsum += __shfl_xor_sync(0xffffffffu, vsum, 1);
            vsum += __shfl_xor_sync(0xffffffffu, vsum, 2);
            if (t == 0) RS[wn * 128 + wm32 + fm * 16 + rh * 8 + g] = vsum;
        }
    float* OS = (float*)(smem + OFF_QH);   // 64KB scratch: [row][d]
    if (wn == 1){
        #pragma unroll
        for (int fm = 0; fm < 2; fm++){
            const int r0 = wm32 + fm * 16 + g, r1 = r0 + 8;
            #pragma unroll
            for (int fn = 0; fn < 16; fn++){
                const int d0 = fn * 8 + t * 2;
                *(float2*)(OS + r0 * 128 + d0) = make_float2(o_acc[fm][fn][0], o_acc[fm][fn][1]);
                *(float2*)(OS + r1 * 128 + d0) = make_float2(o_acc[fm][fn][2], o_acc[fm][fn][3]);
            }
        }
    }
    __syncthreads();
    if (tid < 128){
        float detr = RS[tid] + RS[128 + tid] + g_sc[bh] + 1e-9f;
        float inv = 1.0f / detr;
        ((float*)(smem + OFF_INV))[tid] = inv;
        g_inv[(size_t)bh * N_ + n0 + tid] = inv;
    }
    __syncthreads();

    // ---- wn=0 combines halves, normalizes, writes O ----
    if (wn == 0){
        const float* INV = (const float*)(smem + OFF_INV);
        #pragma unroll
        for (int fm = 0; fm < 2; fm++){
            const int r0 = wm32 + fm * 16 + g, r1 = r0 + 8;
            const float i0 = INV[r0], i1 = INV[r1];
            float* ob0 = out + ((size_t)bh * N_ + n0 + r0) * DH_;
            float* ob1 = out + ((size_t)bh * N_ + n0 + r1) * DH_;
            #pragma unroll
            for (int fn = 0; fn < 16; fn++){
                const int d0 = fn * 8 + t * 2;
                float2 p0 = *(const float2*)(OS + r0 * 128 + d0);
                float2 p1 = *(const float2*)(OS + r1 * 128 + d0);
                *(float2*)(ob0 + d0) = make_float2((o_acc[fm][fn][0] + p0.x) * i0,
                                                   (o_acc[fm][fn][1] + p0.y) * i0);
                *(float2*)(ob1 + d0) = make_float2((o_acc[fm][fn][2] + p1.x) * i1,
                                                   (o_acc[fm][fn][3] + p1.y) * i1);
            }
        }
    }
}

// ---------------- scores normalization ----------------
__global__ void k_scale(float* __restrict__ scores){
    const size_t total4 = (size_t)BH_ * N_ * N_ / 4;
    const size_t stride = (size_t)gridDim.x * blockDim.x;
    float4* p = (float4*)scores;
    for (size_t i = (size_t)blockIdx.x * blockDim.x + threadIdx.x; i < total4; i += stride){
        const size_t row = i >> 8;
        const float invd = g_inv[row];
        float4 x = p[i];
        x.x *= invd; x.y *= invd; x.z *= invd; x.w *= invd;
        p[i] = x;
    }
}

extern "C" void kernel_launch(void* const* d_in, const int* in_sizes, int n_in,
                              void* d_out, int out_size)
{
    const float* q  = (const float*)d_in[0];
    const float* k  = (const float*)d_in[1];
    const float* v  = (const float*)d_in[2];
    const float* c  = (const float*)d_in[3];
    const float* dq = (const float*)d_in[4];
    const float* dk = (const float*)d_in[5];
    const float* ww = (const float*)d_in[6];
    const float* bw = (const float*)d_in[7];
    const float* wb = (const float*)d_in[8];
    const float* bb = (const float*)d_in[9];

    float* out    = (float*)d_out;
    float* scores = out + (size_t)BH_ * N_ * DH_;

    cudaFuncSetAttribute(k_main, cudaFuncAttributeMaxDynamicSharedMemorySize, SMEM_TOTAL);

    k_sc<<<BH_, 256>>>(c);
    k_main<<<BH_ * (N_ / BM), 256, SMEM_TOTAL>>>(q, k, v, dq, dk, ww, bw, wb, bb, out, scores);
    k_scale<<<8192, 256>>>(scores);
}

// round 10
// speedup vs baseline: 2.2694x; 1.1375x over previous
#include <cuda_runtime.h>
#include <cuda_fp16.h>
#include <math.h>
#include <stdint.h>

#define B_  4
#define H_  8
#define N_  1024
#define DH_ 128
#define BH_ (B_*H_)
#define BM  128
#define MT  128
#define NTILES (N_/MT)
#define SCALE_Q 0.08838834764831845f  /* 1/sqrt(128) */

// ---------------- smem layout (bytes) ----------------
#define OFF_QH   0
#define OFF_QL   32768
#define OFF_KH   65536
#define OFF_VH   98304
#define OFF_VL   131072
#define OFF_DK   163840              /* float4[128] = 2048 */
#define OFF_RS   165888              /* float[256]  = 1024 */
#define OFF_INV  166912              /* float[128]  = 512  */
#define SMEM_TOTAL 167424
/* O-reduction scratch reuses OFF_QH..OFF_KH (64KB, dead after last QK) */

__device__ float g_sc[BH_];
__device__ float g_inv[BH_*N_];

// ---------------- helpers ----------------
__device__ __forceinline__ uint32_t smem_u32(const void* p){
    uint32_t a;
    asm("{ .reg .u64 t; cvta.to.shared.u64 t, %1; cvt.u32.u64 %0, t; }" : "=r"(a) : "l"(p));
    return a;
}
__device__ __forceinline__ void ldsm4(uint32_t* r, uint32_t addr){
    asm volatile("ldmatrix.sync.aligned.m8n8.x4.shared.b16 {%0,%1,%2,%3}, [%4];"
        : "=r"(r[0]), "=r"(r[1]), "=r"(r[2]), "=r"(r[3]) : "r"(addr));
}
__device__ __forceinline__ void ldsm4t(uint32_t* r, uint32_t addr){
    asm volatile("ldmatrix.sync.aligned.m8n8.x4.trans.shared.b16 {%0,%1,%2,%3}, [%4];"
        : "=r"(r[0]), "=r"(r[1]), "=r"(r[2]), "=r"(r[3]) : "r"(addr));
}
__device__ __forceinline__ void mma16816(float* c, const uint32_t* a, const uint32_t* b){
    asm volatile("mma.sync.aligned.m16n8k16.row.col.f32.f16.f16.f32 "
        "{%0,%1,%2,%3}, {%4,%5,%6,%7}, {%8,%9}, {%0,%1,%2,%3};"
        : "+f"(c[0]), "+f"(c[1]), "+f"(c[2]), "+f"(c[3])
        : "r"(a[0]), "r"(a[1]), "r"(a[2]), "r"(a[3]), "r"(b[0]), "r"(b[1]));
}

// swizzled byte offset in a 128x128 half tile (2 atom-cols of 64, SW128 per 128B row)
__device__ __forceinline__ int swzel(int row, int col){
    return ((col >> 6) << 14) + ((row >> 3) << 10) + ((row & 7) << 7)
         + ((((col & 63) << 1)) ^ ((row & 7) << 4));
}

__device__ __forceinline__ uint32_t h2u(__half2 x){ return *reinterpret_cast<uint32_t*>(&x); }
__device__ __forceinline__ __half2 pack2(float a, float b){
    return __float22half2_rn(make_float2(a, b));
}

// hi+lo fp16 split store (Q, V)
__device__ __forceinline__ void split_store4(char* ph, char* pl, float4 v){
    __half2 h01 = pack2(v.x, v.y);
    __half2 h23 = pack2(v.z, v.w);
    float l0 = v.x - __half2float(__low2half(h01));
    float l1 = v.y - __half2float(__high2half(h01));
    float l2 = v.z - __half2float(__low2half(h23));
    float l3 = v.w - __half2float(__high2half(h23));
    *(uint2*)ph = make_uint2(h2u(h01), h2u(h23));
    *(uint2*)pl = make_uint2(h2u(pack2(l0, l1)), h2u(pack2(l2, l3)));
}
// hi-only fp16 store (K)
__device__ __forceinline__ void hi_store4(char* ph, float4 v){
    *(uint2*)ph = make_uint2(h2u(pack2(v.x, v.y)), h2u(pack2(v.z, v.w)));
}

// ---------------- kernel A: per-(b,h) sum softplus(c) ----------------
__global__ void k_sc(const float* __restrict__ c){
    const int bh = blockIdx.x, tid = threadIdx.x;
    const float* cp = c + (size_t)bh * N_;
    float s = 0.0f;
    for (int i = tid; i < N_; i += 256){
        float x = cp[i];
        s += fmaxf(x, 0.0f) + log1pf(__expf(-fabsf(x)));
    }
    #pragma unroll
    for (int o = 16; o; o >>= 1) s += __shfl_xor_sync(0xffffffffu, s, o);
    __shared__ float red[8];
    if ((tid & 31) == 0) red[tid >> 5] = s;
    __syncthreads();
    if (tid == 0){
        float t = 0.0f;
        #pragma unroll
        for (int i = 0; i < 8; i++) t += red[i];
        g_sc[bh] = t;
    }
}

// ---------------- main tensor-core kernel ----------------
extern __shared__ __align__(16) char smem[];

__global__ __launch_bounds__(256)
void k_main(const float* __restrict__ q, const float* __restrict__ k,
            const float* __restrict__ v, const float* __restrict__ d_q,
            const float* __restrict__ d_k,
            const float* __restrict__ w_w, const float* __restrict__ b_w,
            const float* __restrict__ w_b, const float* __restrict__ b_b,
            float* __restrict__ out, float* __restrict__ scores)
{
    const int tid  = threadIdx.x;
    const int w    = tid >> 5, lane = tid & 31;
    const int g    = lane >> 2, t = lane & 3;
    const int bh   = blockIdx.x >> 3, rt = blockIdx.x & 7;
    const int b    = bh >> 3, h = bh & 7;
    const int n0   = rt * BM;
    const int wm32 = (w & 3) * 32;
    const int wn   = w >> 2;
    const int nb64 = wn * 64;

    const uint32_t sb  = smem_u32(smem);
    const uint32_t sQH = sb + OFF_QH, sQL = sb + OFF_QL;
    const uint32_t sKH = sb + OFF_KH;
    const uint32_t sVH = sb + OFF_VH, sVL = sb + OFF_VL;

    const float* qbase = q + ((size_t)bh * N_ + n0) * DH_;
    const float* kbase = k + (size_t)bh * N_ * DH_;
    const float* vbase = v + (size_t)bh * N_ * DH_;
    float* scbase = scores + ((size_t)bh * N_ + n0) * (size_t)N_;

    // ---- load + split Q (pre-scaled), hi+lo fp16 ----
    #pragma unroll 4
    for (int it = 0; it < 16; it++){
        int idx = it * 256 + tid;
        int row = idx >> 5, c4 = (idx & 31) * 4;
        float4 qa = *(const float4*)(qbase + (size_t)row * DH_ + c4);
        qa.x *= SCALE_Q; qa.y *= SCALE_Q; qa.z *= SCALE_Q; qa.w *= SCALE_Q;
        int off = swzel(row, c4);
        split_store4(smem + OFF_QH + off, smem + OFF_QL + off, qa);
    }

    // ---- per-lane row constants (4 rows: fm x rowhalf) ----
    const float ww = w_w[h], bw = b_w[h], wb = w_b[h], bb = b_b[h];
    const float m2w = -2.0f * ww, m2b = -2.0f * wb;
    float dqx_[2][2], dqy_[2][2], dqz_[2][2], aq_[2][2], ab_[2][2];
    #pragma unroll
    for (int fm = 0; fm < 2; fm++)
        #pragma unroll
        for (int rh = 0; rh < 2; rh++){
            int r = wm32 + fm * 16 + rh * 8 + g;
            float4 dv = *(const float4*)(d_q + ((size_t)b * N_ + n0 + r) * 4);
            dqx_[fm][rh] = dv.x; dqy_[fm][rh] = dv.y; dqz_[fm][rh] = dv.z;
            float sq = dv.x*dv.x + dv.y*dv.y + dv.z*dv.z;
            aq_[fm][rh] = fmaf(ww, sq, bw);
            ab_[fm][rh] = fmaf(wb, sq, bb);
        }

    // O accumulator: full d=128 per warp, k restricted to this warp's 64-col slab
    float o_acc[2][16][4];
    #pragma unroll
    for (int fm = 0; fm < 2; fm++)
        #pragma unroll
        for (int fn = 0; fn < 16; fn++)
            #pragma unroll
            for (int e = 0; e < 4; e++) o_acc[fm][fn][e] = 0.0f;
    float rs_[2][2] = {{0.0f,0.0f},{0.0f,0.0f}};

    const int aRowOff = (lane & 15), aColOff = ((lane >> 4) << 3);
    const int bRowOff = (lane & 7) + (((lane >> 3) & 1) << 3), bColOff = ((lane >> 4) << 3);
    const int vtRow = (((lane >> 4) & 1) << 3) + (lane & 7), vtCol = (((lane >> 3) & 1) << 3);

    for (int mt = 0; mt < NTILES; mt++){
        const int m0 = mt * MT;
        __syncthreads();   // prior tile's MMAs done reading K/V smem

        // ---- load K (hi only) + V (hi+lo) tiles + dk ----
        #pragma unroll 4
        for (int it = 0; it < 16; it++){
            int idx = it * 256 + tid;
            int row = idx >> 5, c4 = (idx & 31) * 4;
            float4 kv = *(const float4*)(kbase + (size_t)(m0 + row) * DH_ + c4);
            float4 vv = *(const float4*)(vbase + (size_t)(m0 + row) * DH_ + c4);
            int off = swzel(row, c4);
            hi_store4(smem + OFF_KH + off, kv);
            split_store4(smem + OFF_VH + off, smem + OFF_VL + off, vv);
        }
        if (tid < 128){
            float4 dv = *(const float4*)(d_k + ((size_t)b * N_ + m0 + tid) * 4);
            ((float4*)(smem + OFF_DK))[tid] =
                make_float4(dv.x, dv.y, dv.z, dv.x*dv.x + dv.y*dv.y + dv.z*dv.z);
        }
        __syncthreads();

        // ---- S = (Qh+Ql) Kh^T : 2-pass fp16 split ----
        float s_acc[2][8][4];
        #pragma unroll
        for (int fm = 0; fm < 2; fm++)
            #pragma unroll
            for (int fn = 0; fn < 8; fn++)
                #pragma unroll
                for (int e = 0; e < 4; e++) s_acc[fm][fn][e] = 0.0f;

        #pragma unroll
        for (int ks = 0; ks < 8; ks++){
            const int kc = ks * 16;
            uint32_t aqh0[4], aqh1[4], aql0[4], aql1[4];
            ldsm4(aqh0, sQH + swzel(wm32 +      aRowOff, kc + aColOff));
            ldsm4(aqh1, sQH + swzel(wm32 + 16 + aRowOff, kc + aColOff));
            ldsm4(aql0, sQL + swzel(wm32 +      aRowOff, kc + aColOff));
            ldsm4(aql1, sQL + swzel(wm32 + 16 + aRowOff, kc + aColOff));
            #pragma unroll
            for (int blk = 0; blk < 4; blk++){
                uint32_t bkh[4];
                ldsm4(bkh, sKH + swzel(nb64 + blk * 16 + bRowOff, kc + bColOff));
                #pragma unroll
                for (int sub = 0; sub < 2; sub++){
                    uint32_t b2[2] = { bkh[sub], bkh[2 + sub] };
                    mma16816(s_acc[0][blk*2+sub], aqh0, b2);
                    mma16816(s_acc[1][blk*2+sub], aqh1, b2);
                    mma16816(s_acc[0][blk*2+sub], aql0, b2);
                    mma16816(s_acc[1][blk*2+sub], aql1, b2);
                }
            }
        }

        // ---- map epilogue: dist map + relu, rowsum, scores out, pack P (fp16 hi) ----
        uint32_t pah[2][4][4];
        const float4* dk4s = (const float4*)(smem + OFF_DK);
        #pragma unroll
        for (int fm = 0; fm < 2; fm++){
            #pragma unroll
            for (int fn = 0; fn < 8; fn++){
                const int c0 = nb64 + fn * 8 + t * 2;
                const float4 dA = dk4s[c0];
                const float4 dB = dk4s[c0 + 1];
                float p[4];
                #pragma unroll
                for (int e = 0; e < 4; e++){
                    const int rh = e >> 1;
                    const float4 dk = (e & 1) ? dB : dA;
                    float t3 = fmaf(dqx_[fm][rh], dk.x,
                               fmaf(dqy_[fm][rh], dk.y, dqz_[fm][rh] * dk.z));
                    float yw = fmaf(m2w, t3, fmaf(ww, dk.w, aq_[fm][rh]));
                    float db = fmaf(m2b, t3, fmaf(wb, dk.w, ab_[fm][rh]));
                    float z  = fmaxf(fabsf(yw) * -1.4426950408889634f, -126.0f);
                    float ex; asm("ex2.approx.f32 %0, %1;" : "=f"(ex) : "f"(z));
                    float lg; asm("lg2.approx.f32 %0, %1;" : "=f"(lg) : "f"(1.0f + ex));
                    float sp = fmaf(0.6931471805599453f, lg, fmaxf(-yw, 0.0f));
                    float pv = fmaf(s_acc[fm][fn][e], sp, db);
                    pv = fmaxf(pv, 0.0f);
                    p[e] = pv;
                    rs_[fm][rh] += pv;
                }
                const int r0 = wm32 + fm * 16 + g, r1 = r0 + 8;
                *(float2*)(scbase + (size_t)r0 * N_ + m0 + c0) = make_float2(p[0], p[1]);
                *(float2*)(scbase + (size_t)r1 * N_ + m0 + c0) = make_float2(p[2], p[3]);
                // pack C-frag -> A-frag (registers), fp16 hi only
                const int kb = fn >> 1, base = (fn & 1) * 2;
                pah[fm][kb][base + 0] = h2u(pack2(p[0], p[1]));
                pah[fm][kb][base + 1] = h2u(pack2(p[2], p[3]));
            }
        }

        // ---- O += Ph (Vh + Vl) : 2-pass fp16 split (A from registers) ----
        #pragma unroll
        for (int ks = 0; ks < 4; ks++){
            const int krow = nb64 + ks * 16;
            #pragma unroll
            for (int blk = 0; blk < 8; blk++){
                uint32_t bvh[4], bvl[4];
                ldsm4t(bvh, sVH + swzel(krow + vtRow, blk * 16 + vtCol));
                #pragma unroll
                for (int sub = 0; sub < 2; sub++){
                    uint32_t b2[2] = { bvh[sub], bvh[2 + sub] };
                    mma16816(o_acc[0][blk*2+sub], pah[0][ks], b2);
                    mma16816(o_acc[1][blk*2+sub], pah[1][ks], b2);
                }
                ldsm4t(bvl, sVL + swzel(krow + vtRow, blk * 16 + vtCol));
                #pragma unroll
                for (int sub = 0; sub < 2; sub++){
                    uint32_t b2[2] = { bvl[sub], bvl[2 + sub] };
                    mma16816(o_acc[0][blk*2+sub], pah[0][ks], b2);
                    mma16816(o_acc[1][blk*2+sub], pah[1][ks], b2);
                }
            }
        }
    }

    // ---- rowsum reduce; wn=1 stages O partial into (dead) Q smem ----
    float* RS = (float*)(smem + OFF_RS);
    #pragma unroll
    for (int fm = 0; fm < 2; fm++)
        #pragma unroll
        for (int rh = 0; rh < 2; rh++){
            float vsum = rs_[fm][rh];
            vsum += __shfl_xor_sync(0xffffffffu, vsum, 1);
            vsum += __shfl_xor_sync(0xffffffffu, vsum, 2);
            if (t == 0) RS[wn * 128 + wm32 + fm * 16 + rh * 8 + g] = vsum;
        }
    float* OS = (float*)(smem + OFF_QH);   // 64KB scratch: [row][d]
    if (wn == 1){
        #pragma unroll
        for (int fm = 0; fm < 2; fm++){
            const int r0 = wm32 + fm * 16 + g, r1 = r0 + 8;
            #pragma unroll
            for (int fn = 0; fn < 16; fn++){
                const int d0 = fn * 8 + t * 2;
                *(float2*)(OS + r0 * 128 + d0) = make_float2(o_acc[fm][fn][0], o_acc[fm][fn][1]);
                *(float2*)(OS + r1 * 128 + d0) = make_float2(o_acc[fm][fn][2], o_acc[fm][fn][3]);
            }
        }
    }
    __syncthreads();
    if (tid < 128){
        float detr = RS[tid] + RS[128 + tid] + g_sc[bh] + 1e-9f;
        float inv = 1.0f / detr;
        ((float*)(smem + OFF_INV))[tid] = inv;
        g_inv[(size_t)bh * N_ + n0 + tid] = inv;
    }
    __syncthreads();

    // ---- wn=0 combines halves, normalizes, writes O ----
    if (wn == 0){
        const float* INV = (const float*)(smem + OFF_INV);
        #pragma unroll
        for (int fm = 0; fm < 2; fm++){
            const int r0 = wm32 + fm * 16 + g, r1 = r0 + 8;
            const float i0 = INV[r0], i1 = INV[r1];
            float* ob0 = out + ((size_t)bh * N_ + n0 + r0) * DH_;
            float* ob1 = out + ((size_t)bh * N_ + n0 + r1) * DH_;
            #pragma unroll
            for (int fn = 0; fn < 16; fn++){
                const int d0 = fn * 8 + t * 2;
                float2 p0 = *(const float2*)(OS + r0 * 128 + d0);
                float2 p1 = *(const float2*)(OS + r1 * 128 + d0);
                *(float2*)(ob0 + d0) = make_float2((o_acc[fm][fn][0] + p0.x) * i0,
                                                   (o_acc[fm][fn][1] + p0.y) * i0);
                *(float2*)(ob1 + d0) = make_float2((o_acc[fm][fn][2] + p1.x) * i1,
                                                   (o_acc[fm][fn][3] + p1.y) * i1);
            }
        }
    }
}

// ---------------- scores normalization ----------------
__global__ void k_scale(float* __restrict__ scores){
    const size_t total4 = (size_t)BH_ * N_ * N_ / 4;
    const size_t stride = (size_t)gridDim.x * blockDim.x;
    float4* p = (float4*)scores;
    for (size_t i = (size_t)blockIdx.x * blockDim.x + threadIdx.x; i < total4; i += stride){
        const size_t row = i >> 8;
        const float invd = g_inv[row];
        float4 x = p[i];
        x.x *= invd; x.y *= invd; x.z *= invd; x.w *= invd;
        p[i] = x;
    }
}

extern "C" void kernel_launch(void* const* d_in, const int* in_sizes, int n_in,
                              void* d_out, int out_size)
{
    const float* q  = (const float*)d_in[0];
    const float* k  = (const float*)d_in[1];
    const float* v  = (const float*)d_in[2];
    const float* c  = (const float*)d_in[3];
    const float* dq = (const float*)d_in[4];
    const float* dk = (const float*)d_in[5];
    const float* ww = (const float*)d_in[6];
    const float* bw = (const float*)d_in[7];
    const float* wb = (const float*)d_in[8];
    const float* bb = (const float*)d_in[9];

    float* out    = (float*)d_out;
    float* scores = out + (size_t)BH_ * N_ * DH_;

    cudaFuncSetAttribute(k_main, cudaFuncAttributeMaxDynamicSharedMemorySize, SMEM_TOTAL);

    k_sc<<<BH_, 256>>>(c);
    k_main<<<BH_ * (N_ / BM), 256, SMEM_TOTAL>>>(q, k, v, dq, dk, ww, bw, wb, bb, out, scores);
    k_scale<<<8192, 256>>>(scores);
}

// round 11
// speedup vs baseline: 3.0803x; 1.3574x over previous
#include <cuda_runtime.h>
#include <cuda_fp16.h>
#include <math.h>
#include <stdint.h>

#define B_  4
#define H_  8
#define N_  1024
#define DH_ 128
#define BH_ (B_*H_)
#define NTILES 8
#define SCALE_Q 0.08838834764831845f  /* 1/sqrt(128) */

// ---------------- smem layout (bytes) ----------------
#define OFF_QH   0
#define OFF_QL   32768
#define OFF_K0   65536
#define OFF_K1   98304
#define OFF_V0   131072
#define OFF_V1   163840
#define OFF_DK0  196608              /* float4[128] = 2048 */
#define OFF_DK1  198656
#define OFF_RS   200704              /* float[256] */
#define OFF_INV  201728              /* float[128] */
#define OFF_SC   202240              /* float      */
#define SMEM_TOTAL 202304
/* O-reduction scratch reuses OFF_QH..OFF_K0 (64KB, dead after last QK) */

// ---------------- global scratch (pre-converted fp16 tiles, swizzled) ----------------
__device__ __half g_qh[256*16384];
__device__ __half g_ql[256*16384];
__device__ __half g_kh[256*16384];
__device__ __half g_vh[256*16384];
__device__ float4 g_dk4[B_*N_];
__device__ float  g_inv[BH_*N_];

// ---------------- helpers ----------------
__device__ __forceinline__ uint32_t smem_u32(const void* p){
    uint32_t a;
    asm("{ .reg .u64 t; cvta.to.shared.u64 t, %1; cvt.u32.u64 %0, t; }" : "=r"(a) : "l"(p));
    return a;
}
__device__ __forceinline__ void ldsm4(uint32_t* r, uint32_t addr){
    asm volatile("ldmatrix.sync.aligned.m8n8.x4.shared.b16 {%0,%1,%2,%3}, [%4];"
        : "=r"(r[0]), "=r"(r[1]), "=r"(r[2]), "=r"(r[3]) : "r"(addr));
}
__device__ __forceinline__ void ldsm4t(uint32_t* r, uint32_t addr){
    asm volatile("ldmatrix.sync.aligned.m8n8.x4.trans.shared.b16 {%0,%1,%2,%3}, [%4];"
        : "=r"(r[0]), "=r"(r[1]), "=r"(r[2]), "=r"(r[3]) : "r"(addr));
}
__device__ __forceinline__ void mma16816(float* c, const uint32_t* a, const uint32_t* b){
    asm volatile("mma.sync.aligned.m16n8k16.row.col.f32.f16.f16.f32 "
        "{%0,%1,%2,%3}, {%4,%5,%6,%7}, {%8,%9}, {%0,%1,%2,%3};"
        : "+f"(c[0]), "+f"(c[1]), "+f"(c[2]), "+f"(c[3])
        : "r"(a[0]), "r"(a[1]), "r"(a[2]), "r"(a[3]), "r"(b[0]), "r"(b[1]));
}
// swizzled byte offset in a 128x128 half tile
__device__ __forceinline__ int swzel(int row, int col){
    return ((col >> 6) << 14) + ((row >> 3) << 10) + ((row & 7) << 7)
         + ((((col & 63) << 1)) ^ ((row & 7) << 4));
}
__device__ __forceinline__ uint32_t h2u(__half2 x){ return *reinterpret_cast<uint32_t*>(&x); }
__device__ __forceinline__ __half2 pack2(float a, float b){
    return __float22half2_rn(make_float2(a, b));
}
// cp.async 16B
__device__ __forceinline__ void cpa16(uint32_t sdst, size_t gsrc){
    asm volatile("cp.async.cg.shared.global [%0], [%1], 16;" :: "r"(sdst), "l"(gsrc) : "memory");
}
#define CPA_COMMIT() asm volatile("cp.async.commit_group;" ::: "memory")
#define CPA_WAIT0()  asm volatile("cp.async.wait_group 0;" ::: "memory")

// copy one 32KB tile: 8 x 16B per thread
__device__ __forceinline__ void cp_tile32k(uint32_t sdst, const void* gsrc, int tid){
    size_t gs = __cvta_generic_to_global(gsrc);
    #pragma unroll
    for (int i = 0; i < 8; i++){
        int off = (i * 256 + tid) * 16;
        cpa16(sdst + off, gs + off);
    }
}

// ---------------- prep: fp32 -> swizzled fp16 tiles ----------------
__global__ void k_prep(const float* __restrict__ q, const float* __restrict__ k,
                       const float* __restrict__ v, const float* __restrict__ d_k)
{
    const int blk = blockIdx.x, tid = threadIdx.x;
    if (blk < 768){
        const int which = blk >> 8;           // 0=Q, 1=K, 2=V
        const int tile  = blk & 255;          // bh*8 + tt
        const int bh = tile >> 3, tt = tile & 7;
        const float* src = (which == 0 ? q : (which == 1 ? k : v))
                         + ((size_t)bh * N_ + tt * 128) * DH_;
        char* dh = (char*)((which == 0 ? g_qh : (which == 1 ? g_kh : g_vh))
                         + (size_t)tile * 16384);
        char* dl = (char*)(g_ql + (size_t)tile * 16384);
        #pragma unroll 4
        for (int it = 0; it < 16; it++){
            int idx = it * 256 + tid;
            int row = idx >> 5, c4 = (idx & 31) * 4;
            float4 a = *(const float4*)(src + (size_t)row * DH_ + c4);
            int off = swzel(row, c4);
            if (which == 0){
                a.x *= SCALE_Q; a.y *= SCALE_Q; a.z *= SCALE_Q; a.w *= SCALE_Q;
                __half2 h01 = pack2(a.x, a.y), h23 = pack2(a.z, a.w);
                float l0 = a.x - __half2float(__low2half(h01));
                float l1 = a.y - __half2float(__high2half(h01));
                float l2 = a.z - __half2float(__low2half(h23));
                float l3 = a.w - __half2float(__high2half(h23));
                *(uint2*)(dh + off) = make_uint2(h2u(h01), h2u(h23));
                *(uint2*)(dl + off) = make_uint2(h2u(pack2(l0, l1)), h2u(pack2(l2, l3)));
            } else {
                *(uint2*)(dh + off) = make_uint2(h2u(pack2(a.x, a.y)), h2u(pack2(a.z, a.w)));
            }
        }
    } else {
        int i = (blk - 768) * 256 + tid;      // 0 .. B_*N_-1
        float4 dv = *(const float4*)(d_k + (size_t)i * 4);
        g_dk4[i] = make_float4(dv.x, dv.y, dv.z, dv.x*dv.x + dv.y*dv.y + dv.z*dv.z);
    }
}

// ---------------- main tensor-core kernel ----------------
extern __shared__ __align__(16) char smem[];

__global__ __launch_bounds__(256)
void k_main(const float* __restrict__ c, const float* __restrict__ d_q,
            const float* __restrict__ w_w, const float* __restrict__ b_w,
            const float* __restrict__ w_b, const float* __restrict__ b_b,
            float* __restrict__ out, float* __restrict__ scores)
{
    const int tid  = threadIdx.x;
    const int w    = tid >> 5, lane = tid & 31;
    const int g    = lane >> 2, t = lane & 3;
    const int bh   = blockIdx.x >> 3, rt = blockIdx.x & 7;
    const int b    = bh >> 3, h = bh & 7;
    const int n0   = rt * 128;
    const int wm32 = (w & 3) * 32;
    const int wn   = w >> 2;
    const int nb64 = wn * 64;

    const uint32_t sb  = smem_u32(smem);
    const uint32_t sQH = sb + OFF_QH, sQL = sb + OFF_QL;
    const uint32_t sK[2] = { sb + OFF_K0, sb + OFF_K1 };
    const uint32_t sV[2] = { sb + OFF_V0, sb + OFF_V1 };

    float* scbase = scores + ((size_t)bh * N_ + n0) * (size_t)N_;

    // ---- prologue: issue cp.async for Q (hi+lo) and tile 0, then softplus(c) sum ----
    cp_tile32k(sQH, g_qh + (size_t)blockIdx.x * 16384, tid);
    cp_tile32k(sQL, g_ql + (size_t)blockIdx.x * 16384, tid);
    cp_tile32k(sK[0], g_kh + (size_t)(bh * 8 + 0) * 16384, tid);
    cp_tile32k(sV[0], g_vh + (size_t)(bh * 8 + 0) * 16384, tid);
    if (tid < 128)
        cpa16(sb + OFF_DK0 + tid * 16,
              __cvta_generic_to_global(g_dk4 + (size_t)b * N_) + tid * 16);
    CPA_COMMIT();

    // softplus(c) sum for this bh (overlaps the async copies)
    {
        const float* cp = c + (size_t)bh * N_;
        float s = 0.0f;
        #pragma unroll
        for (int i = 0; i < 4; i++){
            float x = cp[tid + i * 256];
            s += fmaxf(x, 0.0f) + log1pf(__expf(-fabsf(x)));
        }
        #pragma unroll
        for (int o = 16; o; o >>= 1) s += __shfl_xor_sync(0xffffffffu, s, o);
        if (lane == 0) ((float*)(smem + OFF_RS))[w] = s;
    }

    // ---- per-lane row constants ----
    const float ww = w_w[h], bw = b_w[h], wb = w_b[h], bb = b_b[h];
    const float m2w = -2.0f * ww, m2b = -2.0f * wb;
    float dqx_[2][2], dqy_[2][2], dqz_[2][2], aq_[2][2], ab_[2][2];
    #pragma unroll
    for (int fm = 0; fm < 2; fm++)
        #pragma unroll
        for (int rh = 0; rh < 2; rh++){
            int r = wm32 + fm * 16 + rh * 8 + g;
            float4 dv = *(const float4*)(d_q + ((size_t)b * N_ + n0 + r) * 4);
            dqx_[fm][rh] = dv.x; dqy_[fm][rh] = dv.y; dqz_[fm][rh] = dv.z;
            float sq = dv.x*dv.x + dv.y*dv.y + dv.z*dv.z;
            aq_[fm][rh] = fmaf(ww, sq, bw);
            ab_[fm][rh] = fmaf(wb, sq, bb);
        }

    float o_acc[2][16][4];
    #pragma unroll
    for (int fm = 0; fm < 2; fm++)
        #pragma unroll
        for (int fn = 0; fn < 16; fn++)
            #pragma unroll
            for (int e = 0; e < 4; e++) o_acc[fm][fn][e] = 0.0f;
    float rs_[2][2] = {{0.0f,0.0f},{0.0f,0.0f}};

    const int aRowOff = (lane & 15), aColOff = ((lane >> 4) << 3);
    const int bRowOff = (lane & 7) + (((lane >> 3) & 1) << 3), bColOff = ((lane >> 4) << 3);
    const int vtRow = (((lane >> 4) & 1) << 3) + (lane & 7), vtCol = (((lane >> 3) & 1) << 3);

    CPA_WAIT0();
    __syncthreads();
    if (tid == 0){
        const float* red = (const float*)(smem + OFF_RS);
        float ss = 0.0f;
        #pragma unroll
        for (int i = 0; i < 8; i++) ss += red[i];
        *(float*)(smem + OFF_SC) = ss;
    }
    __syncthreads();

    for (int mt = 0; mt < NTILES; mt++){
        const int m0 = mt * 128;
        const int cur = mt & 1;

        // ---- prefetch next tile into the other buffer ----
        if (mt + 1 < NTILES){
            cp_tile32k(sK[1 - cur], g_kh + (size_t)(bh * 8 + mt + 1) * 16384, tid);
            cp_tile32k(sV[1 - cur], g_vh + (size_t)(bh * 8 + mt + 1) * 16384, tid);
            if (tid < 128)
                cpa16(sb + (cur ? OFF_DK0 : OFF_DK1) + tid * 16,
                      __cvta_generic_to_global(g_dk4 + (size_t)b * N_ + (mt + 1) * 128) + tid * 16);
            CPA_COMMIT();
        }

        const uint32_t sKH = sK[cur], sVH = sV[cur];

        // ---- S = (Qh+Ql) Kh^T : 2-pass fp16 split ----
        float s_acc[2][8][4];
        #pragma unroll
        for (int fm = 0; fm < 2; fm++)
            #pragma unroll
            for (int fn = 0; fn < 8; fn++)
                #pragma unroll
                for (int e = 0; e < 4; e++) s_acc[fm][fn][e] = 0.0f;

        #pragma unroll
        for (int ks = 0; ks < 8; ks++){
            const int kc = ks * 16;
            uint32_t aqh0[4], aqh1[4], aql0[4], aql1[4];
            ldsm4(aqh0, sQH + swzel(wm32 +      aRowOff, kc + aColOff));
            ldsm4(aqh1, sQH + swzel(wm32 + 16 + aRowOff, kc + aColOff));
            ldsm4(aql0, sQL + swzel(wm32 +      aRowOff, kc + aColOff));
            ldsm4(aql1, sQL + swzel(wm32 + 16 + aRowOff, kc + aColOff));
            #pragma unroll
            for (int blk = 0; blk < 4; blk++){
                uint32_t bkh[4];
                ldsm4(bkh, sKH + swzel(nb64 + blk * 16 + bRowOff, kc + bColOff));
                #pragma unroll
                for (int sub = 0; sub < 2; sub++){
                    uint32_t b2[2] = { bkh[sub], bkh[2 + sub] };
                    mma16816(s_acc[0][blk*2+sub], aqh0, b2);
                    mma16816(s_acc[1][blk*2+sub], aqh1, b2);
                    mma16816(s_acc[0][blk*2+sub], aql0, b2);
                    mma16816(s_acc[1][blk*2+sub], aql1, b2);
                }
            }
        }

        // ---- map epilogue: dist map + relu, rowsum, scores out, pack P (fp16 hi) ----
        uint32_t pah[2][4][4];
        const float4* dk4s = (const float4*)(smem + (cur ? OFF_DK1 : OFF_DK0));
        #pragma unroll
        for (int fm = 0; fm < 2; fm++){
            #pragma unroll
            for (int fn = 0; fn < 8; fn++){
                const int c0 = nb64 + fn * 8 + t * 2;
                const float4 dA = dk4s[c0];
                const float4 dB = dk4s[c0 + 1];
                float p[4];
                #pragma unroll
                for (int e = 0; e < 4; e++){
                    const int rh = e >> 1;
                    const float4 dk = (e & 1) ? dB : dA;
                    float t3 = fmaf(dqx_[fm][rh], dk.x,
                               fmaf(dqy_[fm][rh], dk.y, dqz_[fm][rh] * dk.z));
                    float yw = fmaf(m2w, t3, fmaf(ww, dk.w, aq_[fm][rh]));
                    float db = fmaf(m2b, t3, fmaf(wb, dk.w, ab_[fm][rh]));
                    float z  = fmaxf(fabsf(yw) * -1.4426950408889634f, -126.0f);
                    float ex; asm("ex2.approx.f32 %0, %1;" : "=f"(ex) : "f"(z));
                    float lg; asm("lg2.approx.f32 %0, %1;" : "=f"(lg) : "f"(1.0f + ex));
                    float sp = fmaf(0.6931471805599453f, lg, fmaxf(-yw, 0.0f));
                    float pv = fmaf(s_acc[fm][fn][e], sp, db);
                    pv = fmaxf(pv, 0.0f);
                    p[e] = pv;
                    rs_[fm][rh] += pv;
                }
                const int r0 = wm32 + fm * 16 + g, r1 = r0 + 8;
                *(float2*)(scbase + (size_t)r0 * N_ + m0 + c0) = make_float2(p[0], p[1]);
                *(float2*)(scbase + (size_t)r1 * N_ + m0 + c0) = make_float2(p[2], p[3]);
                const int kb = fn >> 1, base = (fn & 1) * 2;
                pah[fm][kb][base + 0] = h2u(pack2(p[0], p[1]));
                pah[fm][kb][base + 1] = h2u(pack2(p[2], p[3]));
            }
        }

        // ---- O += Ph Vh : single pass (A from registers) ----
        #pragma unroll
        for (int ks = 0; ks < 4; ks++){
            const int krow = nb64 + ks * 16;
            #pragma unroll
            for (int blk = 0; blk < 8; blk++){
                uint32_t bvh[4];
                ldsm4t(bvh, sVH + swzel(krow + vtRow, blk * 16 + vtCol));
                #pragma unroll
                for (int sub = 0; sub < 2; sub++){
                    uint32_t b2[2] = { bvh[sub], bvh[2 + sub] };
                    mma16816(o_acc[0][blk*2+sub], pah[0][ks], b2);
                    mma16816(o_acc[1][blk*2+sub], pah[1][ks], b2);
                }
            }
        }

        CPA_WAIT0();
        __syncthreads();
    }

    // ---- rowsum reduce; wn=1 stages O partial into (dead) Q smem ----
    float* RS = (float*)(smem + OFF_RS);
    #pragma unroll
    for (int fm = 0; fm < 2; fm++)
        #pragma unroll
        for (int rh = 0; rh < 2; rh++){
            float vsum = rs_[fm][rh];
            vsum += __shfl_xor_sync(0xffffffffu, vsum, 1);
            vsum += __shfl_xor_sync(0xffffffffu, vsum, 2);
            if (t == 0) RS[wn * 128 + wm32 + fm * 16 + rh * 8 + g] = vsum;
        }
    float* OS = (float*)(smem + OFF_QH);   // 64KB scratch: [row][d]
    if (wn == 1){
        #pragma unroll
        for (int fm = 0; fm < 2; fm++){
            const int r0 = wm32 + fm * 16 + g, r1 = r0 + 8;
            #pragma unroll
            for (int fn = 0; fn < 16; fn++){
                const int d0 = fn * 8 + t * 2;
                *(float2*)(OS + r0 * 128 + d0) = make_float2(o_acc[fm][fn][0], o_acc[fm][fn][1]);
                *(float2*)(OS + r1 * 128 + d0) = make_float2(o_acc[fm][fn][2], o_acc[fm][fn][3]);
            }
        }
    }
    __syncthreads();
    if (tid < 128){
        float detr = RS[tid] + RS[128 + tid] + *(const float*)(smem + OFF_SC) + 1e-9f;
        float inv = 1.0f / detr;
        ((float*)(smem + OFF_INV))[tid] = inv;
        g_inv[(size_t)bh * N_ + n0 + tid] = inv;
    }
    __syncthreads();

    // ---- wn=0 combines halves, normalizes, writes O ----
    if (wn == 0){
        const float* INV = (const float*)(smem + OFF_INV);
        #pragma unroll
        for (int fm = 0; fm < 2; fm++){
            const int r0 = wm32 + fm * 16 + g, r1 = r0 + 8;
            const float i0 = INV[r0], i1 = INV[r1];
            float* ob0 = out + ((size_t)bh * N_ + n0 + r0) * DH_;
            float* ob1 = out + ((size_t)bh * N_ + n0 + r1) * DH_;
            #pragma unroll
            for (int fn = 0; fn < 16; fn++){
                const int d0 = fn * 8 + t * 2;
                float2 p0 = *(const float2*)(OS + r0 * 128 + d0);
                float2 p1 = *(const float2*)(OS + r1 * 128 + d0);
                *(float2*)(ob0 + d0) = make_float2((o_acc[fm][fn][0] + p0.x) * i0,
                                                   (o_acc[fm][fn][1] + p0.y) * i0);
                *(float2*)(ob1 + d0) = make_float2((o_acc[fm][fn][2] + p1.x) * i1,
                                                   (o_acc[fm][fn][3] + p1.y) * i1);
            }
        }
    }
}

// ---------------- scores normalization ----------------
__global__ void k_scale(float* __restrict__ scores){
    const size_t total4 = (size_t)BH_ * N_ * N_ / 4;
    const size_t stride = (size_t)gridDim.x * blockDim.x;
    float4* p = (float4*)scores;
    for (size_t i = (size_t)blockIdx.x * blockDim.x + threadIdx.x; i < total4; i += stride){
        const size_t row = i >> 8;
        const float invd = g_inv[row];
        float4 x = p[i];
        x.x *= invd; x.y *= invd; x.z *= invd; x.w *= invd;
        p[i] = x;
    }
}

extern "C" void kernel_launch(void* const* d_in, const int* in_sizes, int n_in,
                              void* d_out, int out_size)
{
    const float* q  = (const float*)d_in[0];
    const float* k  = (const float*)d_in[1];
    const float* v  = (const float*)d_in[2];
    const float* c  = (const float*)d_in[3];
    const float* dq = (const float*)d_in[4];
    const float* dk = (const float*)d_in[5];
    const float* ww = (const float*)d_in[6];
    const float* bw = (const float*)d_in[7];
    const float* wb = (const float*)d_in[8];
    const float* bb = (const float*)d_in[9];

    float* out    = (float*)d_out;
    float* scores = out + (size_t)BH_ * N_ * DH_;

    cudaFuncSetAttribute(k_main, cudaFuncAttributeMaxDynamicSharedMemorySize, SMEM_TOTAL);

    k_prep<<<784, 256>>>(q, k, v, dk);
    k_main<<<BH_ * 8, 256, SMEM_TOTAL>>>(c, dq, ww, bw, wb, bb, out, scores);
    k_scale<<<8192, 256>>>(scores);
}

// round 13
// speedup vs baseline: 3.6336x; 1.1796x over previous
#include <cuda_runtime.h>
#include <cuda_fp16.h>
#include <math.h>
#include <stdint.h>

#define B_  4
#define H_  8
#define N_  1024
#define DH_ 128
#define BH_ (B_*H_)
#define NTILES 8
#define SCALE_Q 0.08838834764831845f  /* 1/sqrt(128) */

// ---------------- smem layout (bytes) ----------------
#define OFF_QH   0
#define OFF_K0   32768
#define OFF_K1   65536
#define OFF_V0   98304
#define OFF_V1   131072
#define OFF_DK0  163840              /* float4[128] = 2048 */
#define OFF_DK1  165888
#define OFF_RS   167936              /* float[256] */
#define OFF_INV  168960              /* float[128] */
#define OFF_SC   169472              /* float      */
#define SMEM_TOTAL 169536
/* O-reduction scratch (64KB) reuses OFF_QH..OFF_K1 at the end */

// ---------------- global scratch (pre-converted fp16 tiles, swizzled) ----------------
__device__ __half g_qh[256*16384];
__device__ __half g_kh[256*16384];
__device__ __half g_vh[256*16384];
__device__ float4 g_dk4[B_*N_];
__device__ float  g_inv[BH_*N_];

// ---------------- helpers ----------------
__device__ __forceinline__ uint32_t smem_u32(const void* p){
    uint32_t a;
    asm("{ .reg .u64 t; cvta.to.shared.u64 t, %1; cvt.u32.u64 %0, t; }" : "=r"(a) : "l"(p));
    return a;
}
__device__ __forceinline__ void ldsm4(uint32_t* r, uint32_t addr){
    asm volatile("ldmatrix.sync.aligned.m8n8.x4.shared.b16 {%0,%1,%2,%3}, [%4];"
        : "=r"(r[0]), "=r"(r[1]), "=r"(r[2]), "=r"(r[3]) : "r"(addr));
}
__device__ __forceinline__ void ldsm4t(uint32_t* r, uint32_t addr){
    asm volatile("ldmatrix.sync.aligned.m8n8.x4.trans.shared.b16 {%0,%1,%2,%3}, [%4];"
        : "=r"(r[0]), "=r"(r[1]), "=r"(r[2]), "=r"(r[3]) : "r"(addr));
}
__device__ __forceinline__ void mma16816(float* c, const uint32_t* a, const uint32_t* b){
    asm volatile("mma.sync.aligned.m16n8k16.row.col.f32.f16.f16.f32 "
        "{%0,%1,%2,%3}, {%4,%5,%6,%7}, {%8,%9}, {%0,%1,%2,%3};"
        : "+f"(c[0]), "+f"(c[1]), "+f"(c[2]), "+f"(c[3])
        : "r"(a[0]), "r"(a[1]), "r"(a[2]), "r"(a[3]), "r"(b[0]), "r"(b[1]));
}
// swizzled byte offset in a 128x128 half tile
__device__ __forceinline__ int swzel(int row, int col){
    return ((col >> 6) << 14) + ((row >> 3) << 10) + ((row & 7) << 7)
         + ((((col & 63) << 1)) ^ ((row & 7) << 4));
}
__device__ __forceinline__ uint32_t h2u(__half2 x){ return *reinterpret_cast<uint32_t*>(&x); }
__device__ __forceinline__ __half2 pack2(float a, float b){
    return __float22half2_rn(make_float2(a, b));
}
// cp.async 16B
__device__ __forceinline__ void cpa16(uint32_t sdst, size_t gsrc){
    asm volatile("cp.async.cg.shared.global [%0], [%1], 16;" :: "r"(sdst), "l"(gsrc) : "memory");
}
#define CPA_COMMIT() asm volatile("cp.async.commit_group;" ::: "memory")
#define CPA_WAIT0()  asm volatile("cp.async.wait_group 0;" ::: "memory")

// copy one 32KB tile: 8 x 16B per thread
__device__ __forceinline__ void cp_tile32k(uint32_t sdst, const void* gsrc, int tid){
    size_t gs = __cvta_generic_to_global(gsrc);
    #pragma unroll
    for (int i = 0; i < 8; i++){
        int off = (i * 256 + tid) * 16;
        cpa16(sdst + off, gs + off);
    }
}

// ---------------- prep: fp32 -> swizzled fp16 tiles ----------------
__global__ void k_prep(const float* __restrict__ q, const float* __restrict__ k,
                       const float* __restrict__ v, const float* __restrict__ d_k)
{
    const int blk = blockIdx.x, tid = threadIdx.x;
    if (blk < 768){
        const int which = blk >> 8;           // 0=Q, 1=K, 2=V
        const int tile  = blk & 255;          // bh*8 + tt
        const int bh = tile >> 3, tt = tile & 7;
        const float* src = (which == 0 ? q : (which == 1 ? k : v))
                         + ((size_t)bh * N_ + tt * 128) * DH_;
        char* dh = (char*)((which == 0 ? g_qh : (which == 1 ? g_kh : g_vh))
                         + (size_t)tile * 16384);
        const float sc = (which == 0) ? SCALE_Q : 1.0f;
        #pragma unroll 4
        for (int it = 0; it < 16; it++){
            int idx = it * 256 + tid;
            int row = idx >> 5, c4 = (idx & 31) * 4;
            float4 a = *(const float4*)(src + (size_t)row * DH_ + c4);
            a.x *= sc; a.y *= sc; a.z *= sc; a.w *= sc;
            int off = swzel(row, c4);
            *(uint2*)(dh + off) = make_uint2(h2u(pack2(a.x, a.y)), h2u(pack2(a.z, a.w)));
        }
    } else {
        int i = (blk - 768) * 256 + tid;      // 0 .. B_*N_-1
        float4 dv = *(const float4*)(d_k + (size_t)i * 4);
        g_dk4[i] = make_float4(dv.x, dv.y, dv.z, dv.x*dv.x + dv.y*dv.y + dv.z*dv.z);
    }
}

// ---------------- main tensor-core kernel ----------------
extern __shared__ __align__(16) char smem[];

__global__ __launch_bounds__(256)
void k_main(const float* __restrict__ c, const float* __restrict__ d_q,
            const float* __restrict__ w_w, const float* __restrict__ b_w,
            const float* __restrict__ w_b, const float* __restrict__ b_b,
            float* __restrict__ out, float* __restrict__ scores)
{
    const int tid  = threadIdx.x;
    const int w    = tid >> 5, lane = tid & 31;
    const int g    = lane >> 2, t = lane & 3;
    const int bh   = blockIdx.x >> 3, rt = blockIdx.x & 7;
    const int b    = bh >> 3, h = bh & 7;
    const int n0   = rt * 128;
    const int wm32 = (w & 3) * 32;
    const int wn   = w >> 2;
    const int nb64 = wn * 64;

    const uint32_t sb  = smem_u32(smem);
    const uint32_t sQH = sb + OFF_QH;
    const uint32_t sK[2] = { sb + OFF_K0, sb + OFF_K1 };
    const uint32_t sV[2] = { sb + OFF_V0, sb + OFF_V1 };

    float* scbase = scores + ((size_t)bh * N_ + n0) * (size_t)N_;

    // ---- prologue: issue cp.async for Q and tile 0, then softplus(c) sum ----
    cp_tile32k(sQH, g_qh + (size_t)blockIdx.x * 16384, tid);
    cp_tile32k(sK[0], g_kh + (size_t)(bh * 8 + 0) * 16384, tid);
    cp_tile32k(sV[0], g_vh + (size_t)(bh * 8 + 0) * 16384, tid);
    if (tid < 128)
        cpa16(sb + OFF_DK0 + tid * 16,
              __cvta_generic_to_global(g_dk4 + (size_t)b * N_) + tid * 16);
    CPA_COMMIT();

    // softplus(c) sum for this bh (overlaps the async copies)
    {
        const float* cp = c + (size_t)bh * N_;
        float s = 0.0f;
        #pragma unroll
        for (int i = 0; i < 4; i++){
            float x = cp[tid + i * 256];
            s += fmaxf(x, 0.0f) + log1pf(__expf(-fabsf(x)));
        }
        #pragma unroll
        for (int o = 16; o; o >>= 1) s += __shfl_xor_sync(0xffffffffu, s, o);
        if (lane == 0) ((float*)(smem + OFF_RS))[w] = s;
    }

    // ---- per-lane row constants ----
    const float ww = w_w[h], bw = b_w[h], wb = w_b[h], bb = b_b[h];
    const float m2w = -2.0f * ww, m2b = -2.0f * wb;
    float dqx_[2][2], dqy_[2][2], dqz_[2][2], aq_[2][2], ab_[2][2];
    #pragma unroll
    for (int fm = 0; fm < 2; fm++)
        #pragma unroll
        for (int rh = 0; rh < 2; rh++){
            int r = wm32 + fm * 16 + rh * 8 + g;
            float4 dv = *(const float4*)(d_q + ((size_t)b * N_ + n0 + r) * 4);
            dqx_[fm][rh] = dv.x; dqy_[fm][rh] = dv.y; dqz_[fm][rh] = dv.z;
            float sq = dv.x*dv.x + dv.y*dv.y + dv.z*dv.z;
            aq_[fm][rh] = fmaf(ww, sq, bw);
            ab_[fm][rh] = fmaf(wb, sq, bb);
        }

    float o_acc[2][16][4];
    #pragma unroll
    for (int fm = 0; fm < 2; fm++)
        #pragma unroll
        for (int fn = 0; fn < 16; fn++)
            #pragma unroll
            for (int e = 0; e < 4; e++) o_acc[fm][fn][e] = 0.0f;
    float rs_[2][2] = {{0.0f,0.0f},{0.0f,0.0f}};

    const int aRowOff = (lane & 15), aColOff = ((lane >> 4) << 3);
    const int bRowOff = (lane & 7) + (((lane >> 3) & 1) << 3), bColOff = ((lane >> 4) << 3);
    const int vtRow = (((lane >> 4) & 1) << 3) + (lane & 7), vtCol = (((lane >> 3) & 1) << 3);

    CPA_WAIT0();
    __syncthreads();
    if (tid == 0){
        const float* red = (const float*)(smem + OFF_RS);
        float ss = 0.0f;
        #pragma unroll
        for (int i = 0; i < 8; i++) ss += red[i];
        *(float*)(smem + OFF_SC) = ss;
    }
    __syncthreads();

    for (int mt = 0; mt < NTILES; mt++){
        const int m0 = mt * 128;
        const int cur = mt & 1;

        // ---- prefetch next tile into the other buffer ----
        if (mt + 1 < NTILES){
            cp_tile32k(sK[1 - cur], g_kh + (size_t)(bh * 8 + mt + 1) * 16384, tid);
            cp_tile32k(sV[1 - cur], g_vh + (size_t)(bh * 8 + mt + 1) * 16384, tid);
            if (tid < 128)
                cpa16(sb + (cur ? OFF_DK0 : OFF_DK1) + tid * 16,
                      __cvta_generic_to_global(g_dk4 + (size_t)b * N_ + (mt + 1) * 128) + tid * 16);
            CPA_COMMIT();
        }

        const uint32_t sKH = sK[cur], sVH = sV[cur];

        // ---- S = Qh Kh^T : single-pass fp16 ----
        float s_acc[2][8][4];
        #pragma unroll
        for (int fm = 0; fm < 2; fm++)
            #pragma unroll
            for (int fn = 0; fn < 8; fn++)
                #pragma unroll
                for (int e = 0; e < 4; e++) s_acc[fm][fn][e] = 0.0f;

        #pragma unroll
        for (int ks = 0; ks < 8; ks++){
            const int kc = ks * 16;
            uint32_t aqh0[4], aqh1[4];
            ldsm4(aqh0, sQH + swzel(wm32 +      aRowOff, kc + aColOff));
            ldsm4(aqh1, sQH + swzel(wm32 + 16 + aRowOff, kc + aColOff));
            #pragma unroll
            for (int blk = 0; blk < 4; blk++){
                uint32_t bkh[4];
                ldsm4(bkh, sKH + swzel(nb64 + blk * 16 + bRowOff, kc + bColOff));
                #pragma unroll
                for (int sub = 0; sub < 2; sub++){
                    uint32_t b2[2] = { bkh[sub], bkh[2 + sub] };
                    mma16816(s_acc[0][blk*2+sub], aqh0, b2);
                    mma16816(s_acc[1][blk*2+sub], aqh1, b2);
                }
            }
        }

        // ---- map epilogue: dist map + relu, rowsum, scores out, pack P (fp16) ----
        uint32_t pah[2][4][4];
        const float4* dk4s = (const float4*)(smem + (cur ? OFF_DK1 : OFF_DK0));
        #pragma unroll
        for (int fm = 0; fm < 2; fm++){
            #pragma unroll
            for (int fn = 0; fn < 8; fn++){
                const int c0 = nb64 + fn * 8 + t * 2;
                const float4 dA = dk4s[c0];
                const float4 dB = dk4s[c0 + 1];
                float p[4];
                #pragma unroll
                for (int e = 0; e < 4; e++){
                    const int rh = e >> 1;
                    const float4 dk = (e & 1) ? dB : dA;
                    float t3 = fmaf(dqx_[fm][rh], dk.x,
                               fmaf(dqy_[fm][rh], dk.y, dqz_[fm][rh] * dk.z));
                    float yw = fmaf(m2w, t3, fmaf(ww, dk.w, aq_[fm][rh]));
                    float db = fmaf(m2b, t3, fmaf(wb, dk.w, ab_[fm][rh]));
                    float z  = fmaxf(fabsf(yw) * -1.4426950408889634f, -126.0f);
                    float ex; asm("ex2.approx.f32 %0, %1;" : "=f"(ex) : "f"(z));
                    float lg; asm("lg2.approx.f32 %0, %1;" : "=f"(lg) : "f"(1.0f + ex));
                    float sp = fmaf(0.6931471805599453f, lg, fmaxf(-yw, 0.0f));
                    float pv = fmaf(s_acc[fm][fn][e], sp, db);
                    pv = fmaxf(pv, 0.0f);
                    p[e] = pv;
                    rs_[fm][rh] += pv;
                }
                const int r0 = wm32 + fm * 16 + g, r1 = r0 + 8;
                *(float2*)(scbase + (size_t)r0 * N_ + m0 + c0) = make_float2(p[0], p[1]);
                *(float2*)(scbase + (size_t)r1 * N_ + m0 + c0) = make_float2(p[2], p[3]);
                const int kb = fn >> 1, base = (fn & 1) * 2;
                pah[fm][kb][base + 0] = h2u(pack2(p[0], p[1]));
                pah[fm][kb][base + 1] = h2u(pack2(p[2], p[3]));
            }
        }

        // ---- O += Ph Vh : single pass (A from registers) ----
        #pragma unroll
        for (int ks = 0; ks < 4; ks++){
            const int krow = nb64 + ks * 16;
            #pragma unroll
            for (int blk = 0; blk < 8; blk++){
                uint32_t bvh[4];
                ldsm4t(bvh, sVH + swzel(krow + vtRow, blk * 16 + vtCol));
                #pragma unroll
                for (int sub = 0; sub < 2; sub++){
                    uint32_t b2[2] = { bvh[sub], bvh[2 + sub] };
                    mma16816(o_acc[0][blk*2+sub], pah[0][ks], b2);
                    mma16816(o_acc[1][blk*2+sub], pah[1][ks], b2);
                }
            }
        }

        CPA_WAIT0();
        __syncthreads();
    }

    // ---- rowsum reduce; wn=1 stages O partial into (dead) Q/K smem ----
    float* RS = (float*)(smem + OFF_RS);
    #pragma unroll
    for (int fm = 0; fm < 2; fm++)
        #pragma unroll
        for (int rh = 0; rh < 2; rh++){
            float vsum = rs_[fm][rh];
            vsum += __shfl_xor_sync(0xffffffffu, vsum, 1);
            vsum += __shfl_xor_sync(0xffffffffu, vsum, 2);
            if (t == 0) RS[wn * 128 + wm32 + fm * 16 + rh * 8 + g] = vsum;
        }
    float* OS = (float*)(smem + OFF_QH);   // 64KB scratch: [row][d]
    if (wn == 1){
        #pragma unroll
        for (int fm = 0; fm < 2; fm++){
            const int r0 = wm32 + fm * 16 + g, r1 = r0 + 8;
            #pragma unroll
            for (int fn = 0; fn < 16; fn++){
                const int d0 = fn * 8 + t * 2;
                *(float2*)(OS + r0 * 128 + d0) = make_float2(o_acc[fm][fn][0], o_acc[fm][fn][1]);
                *(float2*)(OS + r1 * 128 + d0) = make_float2(o_acc[fm][fn][2], o_acc[fm][fn][3]);
            }
        }
    }
    __syncthreads();
    if (tid < 128){
        float detr = RS[tid] + RS[128 + tid] + *(const float*)(smem + OFF_SC) + 1e-9f;
        float inv = 1.0f / detr;
        ((float*)(smem + OFF_INV))[tid] = inv;
        g_inv[(size_t)bh * N_ + n0 + tid] = inv;
    }
    __syncthreads();

    // ---- wn=0 combines halves, normalizes, writes O ----
    if (wn == 0){
        const float* INV = (const float*)(smem + OFF_INV);
        #pragma unroll
        for (int fm = 0; fm < 2; fm++){
            const int r0 = wm32 + fm * 16 + g, r1 = r0 + 8;
            const float i0 = INV[r0], i1 = INV[r1];
            float* ob0 = out + ((size_t)bh * N_ + n0 + r0) * DH_;
            float* ob1 = out + ((size_t)bh * N_ + n0 + r1) * DH_;
            #pragma unroll
            for (int fn = 0; fn < 16; fn++){
                const int d0 = fn * 8 + t * 2;
                float2 p0 = *(const float2*)(OS + r0 * 128 + d0);
                float2 p1 = *(const float2*)(OS + r1 * 128 + d0);
                *(float2*)(ob0 + d0) = make_float2((o_acc[fm][fn][0] + p0.x) * i0,
                                                   (o_acc[fm][fn][1] + p0.y) * i0);
                *(float2*)(ob1 + d0) = make_float2((o_acc[fm][fn][2] + p1.x) * i1,
                                                   (o_acc[fm][fn][3] + p1.y) * i1);
            }
        }
    }
}

// ---------------- scores normalization ----------------
__global__ void k_scale(float* __restrict__ scores){
    const size_t total4 = (size_t)BH_ * N_ * N_ / 4;
    const size_t stride = (size_t)gridDim.x * blockDim.x;
    float4* p = (float4*)scores;
    for (size_t i = (size_t)blockIdx.x * blockDim.x + threadIdx.x; i < total4; i += stride){
        const size_t row = i >> 8;
        const float invd = g_inv[row];
        float4 x = p[i];
        x.x *= invd; x.y *= invd; x.z *= invd; x.w *= invd;
        p[i] = x;
    }
}

extern "C" void kernel_launch(void* const* d_in, const int* in_sizes, int n_in,
                              void* d_out, int out_size)
{
    const float* q  = (const float*)d_in[0];
    const float* k  = (const float*)d_in[1];
    const float* v  = (const float*)d_in[2];
    const float* c  = (const float*)d_in[3];
    const float* dq = (const float*)d_in[4];
    const float* dk = (const float*)d_in[5];
    const float* ww = (const float*)d_in[6];
    const float* bw = (const float*)d_in[7];
    const float* wb = (const float*)d_in[8];
    const float* bb = (const float*)d_in[9];

    float* out    = (float*)d_out;
    float* scores = out + (size_t)BH_ * N_ * DH_;

    cudaFuncSetAttribute(k_main, cudaFuncAttributeMaxDynamicSharedMemorySize, SMEM_TOTAL);

    k_prep<<<784, 256>>>(q, k, v, dk);
    k_main<<<BH_ * 8, 256, SMEM_TOTAL>>>(c, dq, ww, bw, wb, bb, out, scores);
    k_scale<<<8192, 256>>>(scores);
}

// round 14
// speedup vs baseline: 4.1684x; 1.1472x over previous
#include <cuda_runtime.h>
#include <cuda_fp16.h>
#include <math.h>
#include <stdint.h>

#define B_  4
#define H_  8
#define N_  1024
#define DH_ 128
#define BH_ (B_*H_)
#define NTILES 8
#define SCALE_Q 0.08838834764831845f  /* 1/sqrt(128) */

// ---------------- smem layout (bytes) ----------------
#define OFF_QH   0
#define OFF_K0   32768
#define OFF_K1   65536
#define OFF_V0   98304
#define OFF_V1   131072
#define OFF_DK0  163840              /* float4[128] = 2048 */
#define OFF_DK1  165888
#define OFF_RS   167936              /* float[256] */
#define OFF_INV  168960              /* float[128] */
#define OFF_SC   169472              /* float      */
#define SMEM_TOTAL 169536
/* O-reduction scratch (64KB) reuses OFF_QH..OFF_K1 at the end */

// ---------------- global scratch ----------------
__device__ __half g_qh[256*16384];
__device__ __half g_kh[256*16384];
__device__ __half g_vh[256*16384];
__device__ __half g_p16[(size_t)BH_*N_*N_];   /* raw scores, fp16 */
__device__ float4 g_dk4[B_*N_];
__device__ float  g_inv[BH_*N_];

// ---------------- helpers ----------------
__device__ __forceinline__ uint32_t smem_u32(const void* p){
    uint32_t a;
    asm("{ .reg .u64 t; cvta.to.shared.u64 t, %1; cvt.u32.u64 %0, t; }" : "=r"(a) : "l"(p));
    return a;
}
__device__ __forceinline__ void ldsm4(uint32_t* r, uint32_t addr){
    asm volatile("ldmatrix.sync.aligned.m8n8.x4.shared.b16 {%0,%1,%2,%3}, [%4];"
        : "=r"(r[0]), "=r"(r[1]), "=r"(r[2]), "=r"(r[3]) : "r"(addr));
}
__device__ __forceinline__ void ldsm4t(uint32_t* r, uint32_t addr){
    asm volatile("ldmatrix.sync.aligned.m8n8.x4.trans.shared.b16 {%0,%1,%2,%3}, [%4];"
        : "=r"(r[0]), "=r"(r[1]), "=r"(r[2]), "=r"(r[3]) : "r"(addr));
}
__device__ __forceinline__ void mma16816(float* c, const uint32_t* a, const uint32_t* b){
    asm volatile("mma.sync.aligned.m16n8k16.row.col.f32.f16.f16.f32 "
        "{%0,%1,%2,%3}, {%4,%5,%6,%7}, {%8,%9}, {%0,%1,%2,%3};"
        : "+f"(c[0]), "+f"(c[1]), "+f"(c[2]), "+f"(c[3])
        : "r"(a[0]), "r"(a[1]), "r"(a[2]), "r"(a[3]), "r"(b[0]), "r"(b[1]));
}
// swizzled byte offset in a 128x128 half tile
__device__ __forceinline__ int swzel(int row, int col){
    return ((col >> 6) << 14) + ((row >> 3) << 10) + ((row & 7) << 7)
         + ((((col & 63) << 1)) ^ ((row & 7) << 4));
}
__device__ __forceinline__ uint32_t h2u(__half2 x){ return *reinterpret_cast<uint32_t*>(&x); }
__device__ __forceinline__ __half2 pack2(float a, float b){
    return __float22half2_rn(make_float2(a, b));
}
// cp.async 16B
__device__ __forceinline__ void cpa16(uint32_t sdst, size_t gsrc){
    asm volatile("cp.async.cg.shared.global [%0], [%1], 16;" :: "r"(sdst), "l"(gsrc) : "memory");
}
#define CPA_COMMIT() asm volatile("cp.async.commit_group;" ::: "memory")
#define CPA_WAIT0()  asm volatile("cp.async.wait_group 0;" ::: "memory")

// copy one 32KB tile: 8 x 16B per thread
__device__ __forceinline__ void cp_tile32k(uint32_t sdst, const void* gsrc, int tid){
    size_t gs = __cvta_generic_to_global(gsrc);
    #pragma unroll
    for (int i = 0; i < 8; i++){
        int off = (i * 256 + tid) * 16;
        cpa16(sdst + off, gs + off);
    }
}

// ---------------- prep: fp32 -> swizzled fp16 tiles ----------------
__global__ void k_prep(const float* __restrict__ q, const float* __restrict__ k,
                       const float* __restrict__ v, const float* __restrict__ d_k)
{
    const int blk = blockIdx.x, tid = threadIdx.x;
    if (blk < 768){
        const int which = blk >> 8;           // 0=Q, 1=K, 2=V
        const int tile  = blk & 255;          // bh*8 + tt
        const int bh = tile >> 3, tt = tile & 7;
        const float* src = (which == 0 ? q : (which == 1 ? k : v))
                         + ((size_t)bh * N_ + tt * 128) * DH_;
        char* dh = (char*)((which == 0 ? g_qh : (which == 1 ? g_kh : g_vh))
                         + (size_t)tile * 16384);
        const float sc = (which == 0) ? SCALE_Q : 1.0f;
        #pragma unroll 4
        for (int it = 0; it < 16; it++){
            int idx = it * 256 + tid;
            int row = idx >> 5, c4 = (idx & 31) * 4;
            float4 a = *(const float4*)(src + (size_t)row * DH_ + c4);
            a.x *= sc; a.y *= sc; a.z *= sc; a.w *= sc;
            int off = swzel(row, c4);
            *(uint2*)(dh + off) = make_uint2(h2u(pack2(a.x, a.y)), h2u(pack2(a.z, a.w)));
        }
    } else {
        int i = (blk - 768) * 256 + tid;      // 0 .. B_*N_-1
        float4 dv = *(const float4*)(d_k + (size_t)i * 4);
        g_dk4[i] = make_float4(dv.x, dv.y, dv.z, dv.x*dv.x + dv.y*dv.y + dv.z*dv.z);
    }
}

// ---------------- main tensor-core kernel ----------------
extern __shared__ __align__(16) char smem[];

__global__ __launch_bounds__(256)
void k_main(const float* __restrict__ c, const float* __restrict__ d_q,
            const float* __restrict__ w_w, const float* __restrict__ b_w,
            const float* __restrict__ w_b, const float* __restrict__ b_b,
            float* __restrict__ out)
{
    const int tid  = threadIdx.x;
    const int w    = tid >> 5, lane = tid & 31;
    const int g    = lane >> 2, t = lane & 3;
    const int bh   = blockIdx.x >> 3, rt = blockIdx.x & 7;
    const int b    = bh >> 3, h = bh & 7;
    const int n0   = rt * 128;
    const int wm32 = (w & 3) * 32;
    const int wn   = w >> 2;
    const int nb64 = wn * 64;

    const uint32_t sb  = smem_u32(smem);
    const uint32_t sQH = sb + OFF_QH;
    const uint32_t sK[2] = { sb + OFF_K0, sb + OFF_K1 };
    const uint32_t sV[2] = { sb + OFF_V0, sb + OFF_V1 };

    __half* scbase = g_p16 + ((size_t)bh * N_ + n0) * (size_t)N_;

    // ---- prologue: issue cp.async for Q and tile 0, then softplus(c) sum ----
    cp_tile32k(sQH, g_qh + (size_t)blockIdx.x * 16384, tid);
    cp_tile32k(sK[0], g_kh + (size_t)(bh * 8 + 0) * 16384, tid);
    cp_tile32k(sV[0], g_vh + (size_t)(bh * 8 + 0) * 16384, tid);
    if (tid < 128)
        cpa16(sb + OFF_DK0 + tid * 16,
              __cvta_generic_to_global(g_dk4 + (size_t)b * N_) + tid * 16);
    CPA_COMMIT();

    // softplus(c) sum for this bh (overlaps the async copies)
    {
        const float* cp = c + (size_t)bh * N_;
        float s = 0.0f;
        #pragma unroll
        for (int i = 0; i < 4; i++){
            float x = cp[tid + i * 256];
            s += fmaxf(x, 0.0f) + log1pf(__expf(-fabsf(x)));
        }
        #pragma unroll
        for (int o = 16; o; o >>= 1) s += __shfl_xor_sync(0xffffffffu, s, o);
        if (lane == 0) ((float*)(smem + OFF_RS))[w] = s;
    }

    // ---- per-lane row constants ----
    const float ww = w_w[h], bw = b_w[h], wb = w_b[h], bb = b_b[h];
    const float m2w = -2.0f * ww, m2b = -2.0f * wb;
    float dqx_[2][2], dqy_[2][2], dqz_[2][2], aq_[2][2], ab_[2][2];
    #pragma unroll
    for (int fm = 0; fm < 2; fm++)
        #pragma unroll
        for (int rh = 0; rh < 2; rh++){
            int r = wm32 + fm * 16 + rh * 8 + g;
            float4 dv = *(const float4*)(d_q + ((size_t)b * N_ + n0 + r) * 4);
            dqx_[fm][rh] = dv.x; dqy_[fm][rh] = dv.y; dqz_[fm][rh] = dv.z;
            float sq = dv.x*dv.x + dv.y*dv.y + dv.z*dv.z;
            aq_[fm][rh] = fmaf(ww, sq, bw);
            ab_[fm][rh] = fmaf(wb, sq, bb);
        }

    float o_acc[2][16][4];
    #pragma unroll
    for (int fm = 0; fm < 2; fm++)
        #pragma unroll
        for (int fn = 0; fn < 16; fn++)
            #pragma unroll
            for (int e = 0; e < 4; e++) o_acc[fm][fn][e] = 0.0f;
    float rs_[2][2] = {{0.0f,0.0f},{0.0f,0.0f}};

    const int aRowOff = (lane & 15), aColOff = ((lane >> 4) << 3);
    const int bRowOff = (lane & 7) + (((lane >> 3) & 1) << 3), bColOff = ((lane >> 4) << 3);
    const int vtRow = (((lane >> 4) & 1) << 3) + (lane & 7), vtCol = (((lane >> 3) & 1) << 3);

    CPA_WAIT0();
    __syncthreads();
    if (tid == 0){
        const float* red = (const float*)(smem + OFF_RS);
        float ss = 0.0f;
        #pragma unroll
        for (int i = 0; i < 8; i++) ss += red[i];
        *(float*)(smem + OFF_SC) = ss;
    }
    __syncthreads();

    for (int mt = 0; mt < NTILES; mt++){
        const int m0 = mt * 128;
        const int cur = mt & 1;

        // ---- prefetch next tile into the other buffer ----
        if (mt + 1 < NTILES){
            cp_tile32k(sK[1 - cur], g_kh + (size_t)(bh * 8 + mt + 1) * 16384, tid);
            cp_tile32k(sV[1 - cur], g_vh + (size_t)(bh * 8 + mt + 1) * 16384, tid);
            if (tid < 128)
                cpa16(sb + (cur ? OFF_DK0 : OFF_DK1) + tid * 16,
                      __cvta_generic_to_global(g_dk4 + (size_t)b * N_ + (mt + 1) * 128) + tid * 16);
            CPA_COMMIT();
        }

        const uint32_t sKH = sK[cur], sVH = sV[cur];

        // ---- S = Qh Kh^T : single-pass fp16 ----
        float s_acc[2][8][4];
        #pragma unroll
        for (int fm = 0; fm < 2; fm++)
            #pragma unroll
            for (int fn = 0; fn < 8; fn++)
                #pragma unroll
                for (int e = 0; e < 4; e++) s_acc[fm][fn][e] = 0.0f;

        #pragma unroll
        for (int ks = 0; ks < 8; ks++){
            const int kc = ks * 16;
            uint32_t aqh0[4], aqh1[4];
            ldsm4(aqh0, sQH + swzel(wm32 +      aRowOff, kc + aColOff));
            ldsm4(aqh1, sQH + swzel(wm32 + 16 + aRowOff, kc + aColOff));
            #pragma unroll
            for (int blk = 0; blk < 4; blk++){
                uint32_t bkh[4];
                ldsm4(bkh, sKH + swzel(nb64 + blk * 16 + bRowOff, kc + bColOff));
                #pragma unroll
                for (int sub = 0; sub < 2; sub++){
                    uint32_t b2[2] = { bkh[sub], bkh[2 + sub] };
                    mma16816(s_acc[0][blk*2+sub], aqh0, b2);
                    mma16816(s_acc[1][blk*2+sub], aqh1, b2);
                }
            }
        }

        // ---- map epilogue: dist map + relu, rowsum, P -> fp16 (regs + gmem) ----
        uint32_t pah[2][4][4];
        const float4* dk4s = (const float4*)(smem + (cur ? OFF_DK1 : OFF_DK0));
        #pragma unroll
        for (int fn = 0; fn < 8; fn++){
            const int c0 = nb64 + fn * 8 + t * 2;
            const float4 dA = dk4s[c0];
            const float4 dB = dk4s[c0 + 1];
            const int kb = fn >> 1, base = (fn & 1) * 2;
            #pragma unroll
            for (int fm = 0; fm < 2; fm++){
                float p[4];
                #pragma unroll
                for (int e = 0; e < 4; e++){
                    const int rh = e >> 1;
                    const float4 dk = (e & 1) ? dB : dA;
                    float t3 = fmaf(dqx_[fm][rh], dk.x,
                               fmaf(dqy_[fm][rh], dk.y, dqz_[fm][rh] * dk.z));
                    float yw = fmaf(m2w, t3, fmaf(ww, dk.w, aq_[fm][rh]));
                    float db = fmaf(m2b, t3, fmaf(wb, dk.w, ab_[fm][rh]));
                    float z  = fmaxf(fabsf(yw) * -1.4426950408889634f, -126.0f);
                    float ex; asm("ex2.approx.f32 %0, %1;" : "=f"(ex) : "f"(z));
                    float lg; asm("lg2.approx.f32 %0, %1;" : "=f"(lg) : "f"(1.0f + ex));
                    float sp = fmaf(0.6931471805599453f, lg, fmaxf(-yw, 0.0f));
                    float pv = fmaf(s_acc[fm][fn][e], sp, db);
                    pv = fmaxf(pv, 0.0f);
                    p[e] = pv;
                    rs_[fm][rh] += pv;
                }
                uint32_t h01 = h2u(pack2(p[0], p[1]));
                uint32_t h23 = h2u(pack2(p[2], p[3]));
                pah[fm][kb][base + 0] = h01;
                pah[fm][kb][base + 1] = h23;
                const int r0 = wm32 + fm * 16 + g, r1 = r0 + 8;
                *(uint32_t*)(scbase + (size_t)r0 * N_ + m0 + c0) = h01;
                *(uint32_t*)(scbase + (size_t)r1 * N_ + m0 + c0) = h23;
            }
        }

        // ---- O += Ph Vh : single pass (A from registers) ----
        #pragma unroll
        for (int ks = 0; ks < 4; ks++){
            const int krow = nb64 + ks * 16;
            #pragma unroll
            for (int blk = 0; blk < 8; blk++){
                uint32_t bvh[4];
                ldsm4t(bvh, sVH + swzel(krow + vtRow, blk * 16 + vtCol));
                #pragma unroll
                for (int sub = 0; sub < 2; sub++){
                    uint32_t b2[2] = { bvh[sub], bvh[2 + sub] };
                    mma16816(o_acc[0][blk*2+sub], pah[0][ks], b2);
                    mma16816(o_acc[1][blk*2+sub], pah[1][ks], b2);
                }
            }
        }

        CPA_WAIT0();
        __syncthreads();
    }

    // ---- rowsum reduce; wn=1 stages O partial into (dead) Q/K smem ----
    float* RS = (float*)(smem + OFF_RS);
    #pragma unroll
    for (int fm = 0; fm < 2; fm++)
        #pragma unroll
        for (int rh = 0; rh < 2; rh++){
            float vsum = rs_[fm][rh];
            vsum += __shfl_xor_sync(0xffffffffu, vsum, 1);
            vsum += __shfl_xor_sync(0xffffffffu, vsum, 2);
            if (t == 0) RS[wn * 128 + wm32 + fm * 16 + rh * 8 + g] = vsum;
        }
    float* OS = (float*)(smem + OFF_QH);   // 64KB scratch: [row][d]
    if (wn == 1){
        #pragma unroll
        for (int fm = 0; fm < 2; fm++){
            const int r0 = wm32 + fm * 16 + g, r1 = r0 + 8;
            #pragma unroll
            for (int fn = 0; fn < 16; fn++){
                const int d0 = fn * 8 + t * 2;
                *(float2*)(OS + r0 * 128 + d0) = make_float2(o_acc[fm][fn][0], o_acc[fm][fn][1]);
                *(float2*)(OS + r1 * 128 + d0) = make_float2(o_acc[fm][fn][2], o_acc[fm][fn][3]);
            }
        }
    }
    __syncthreads();
    if (tid < 128){
        float detr = RS[tid] + RS[128 + tid] + *(const float*)(smem + OFF_SC) + 1e-9f;
        float inv = 1.0f / detr;
        ((float*)(smem + OFF_INV))[tid] = inv;
        g_inv[(size_t)bh * N_ + n0 + tid] = inv;
    }
    __syncthreads();

    // ---- wn=0 combines halves, normalizes, writes O ----
    if (wn == 0){
        const float* INV = (const float*)(smem + OFF_INV);
        #pragma unroll
        for (int fm = 0; fm < 2; fm++){
            const int r0 = wm32 + fm * 16 + g, r1 = r0 + 8;
            const float i0 = INV[r0], i1 = INV[r1];
            float* ob0 = out + ((size_t)bh * N_ + n0 + r0) * DH_;
            float* ob1 = out + ((size_t)bh * N_ + n0 + r1) * DH_;
            #pragma unroll
            for (int fn = 0; fn < 16; fn++){
                const int d0 = fn * 8 + t * 2;
                float2 p0 = *(const float2*)(OS + r0 * 128 + d0);
                float2 p1 = *(const float2*)(OS + r1 * 128 + d0);
                *(float2*)(ob0 + d0) = make_float2((o_acc[fm][fn][0] + p0.x) * i0,
                                                   (o_acc[fm][fn][1] + p0.y) * i0);
                *(float2*)(ob1 + d0) = make_float2((o_acc[fm][fn][2] + p1.x) * i1,
                                                   (o_acc[fm][fn][3] + p1.y) * i1);
            }
        }
    }
}

// ---------------- scores normalization: fp16 raw -> fp32 normalized ----------------
__global__ void k_scale(float* __restrict__ scores){
    const size_t total8 = (size_t)BH_ * N_ * N_ / 8;   // units of 8 halves
    const size_t stride = (size_t)gridDim.x * blockDim.x;
    const uint4* src = (const uint4*)g_p16;
    for (size_t i = (size_t)blockIdx.x * blockDim.x + threadIdx.x; i < total8; i += stride){
        const size_t row = i >> 7;          // 128 8-elt units per 1024-col row
        const float invd = g_inv[row];
        uint4 hv = src[i];
        float2 f0 = __half22float2(*(const __half2*)&hv.x);
        float2 f1 = __half22float2(*(const __half2*)&hv.y);
        float2 f2 = __half22float2(*(const __half2*)&hv.z);
        float2 f3 = __half22float2(*(const __half2*)&hv.w);
        float4 o0 = make_float4(f0.x * invd, f0.y * invd, f1.x * invd, f1.y * invd);
        float4 o1 = make_float4(f2.x * invd, f2.y * invd, f3.x * invd, f3.y * invd);
        *(float4*)(scores + i * 8)     = o0;
        *(float4*)(scores + i * 8 + 4) = o1;
    }
}

extern "C" void kernel_launch(void* const* d_in, const int* in_sizes, int n_in,
                              void* d_out, int out_size)
{
    const float* q  = (const float*)d_in[0];
    const float* k  = (const float*)d_in[1];
    const float* v  = (const float*)d_in[2];
    const float* c  = (const float*)d_in[3];
    const float* dq = (const float*)d_in[4];
    const float* dk = (const float*)d_in[5];
    const float* ww = (const float*)d_in[6];
    const float* bw = (const float*)d_in[7];
    const float* wb = (const float*)d_in[8];
    const float* bb = (const float*)d_in[9];

    float* out    = (float*)d_out;
    float* scores = out + (size_t)BH_ * N_ * DH_;

    cudaFuncSetAttribute(k_main, cudaFuncAttributeMaxDynamicSharedMemorySize, SMEM_TOTAL);

    k_prep<<<784, 256>>>(q, k, v, dk);
    k_main<<<BH_ * 8, 256, SMEM_TOTAL>>>(c, dq, ww, bw, wb, bb, out);
    k_scale<<<8192, 256>>>(scores);
}